// round 5
// baseline (speedup 1.0000x reference)
#include <cuda_runtime.h>
#include <math.h>

#define A_N    76725
#define NCLS   80
#define NB     8
#define NTASK  (NB*NCLS)
#define KPRE   256
#define MDPC   100
#define MAXD   100
#define CCAP   3072
#define BUFN   1024
#define NBIN   4096
#define PUSH_T 2.0f

__device__ unsigned long long g_cand[(size_t)NTASK * CCAP];
__device__ int    g_cnt[NTASK];
__device__ float  g_cls_scores[NTASK * MDPC];
__device__ float4 g_cls_boxes[NTASK * MDPC];

__device__ __forceinline__ unsigned fkey32(float x) {
    unsigned b = __float_as_uint(x);
    return (b & 0x80000000u) ? ~b : (b | 0x80000000u);
}

template <int BPT>
__device__ __forceinline__ unsigned suffix_total(const unsigned* hist, unsigned* csum, int tid) {
    unsigned s = 0;
    const int base = tid * BPT;
#pragma unroll
    for (int r = 0; r < BPT; ++r) s += hist[base + r];
    csum[tid] = s;
    __syncthreads();
    for (int off = 1; off < 256; off <<= 1) {
        unsigned add = (tid + off < 256) ? csum[tid + off] : 0u;
        __syncthreads();
        csum[tid] += add;
        __syncthreads();
    }
    return csum[0];
}

template <int BPT>
__device__ __forceinline__ void crossing(const unsigned* hist, const unsigned* csum, int* ctrl,
                                         unsigned target, int tid) {
    unsigned run = (tid + 1 < 256) ? csum[tid + 1] : 0u;
    const int base = tid * BPT;
    for (int i = base + BPT - 1; i >= base; --i) {
        unsigned h = hist[i];
        run += h;
        if (run >= target && run - h < target) { ctrl[0] = i; ctrl[1] = (int)(run - h); }
    }
    __syncthreads();
}

// =====================================================================
__global__ void k_zero() {
    int i = blockIdx.x * 256 + threadIdx.x;
    if (i < NTASK) g_cnt[i] = 0;
}

// =====================================================================
// Kernel 1: stream tile -> smem (pure copy, high MLP), then push scan
// =====================================================================
__global__ void __launch_bounds__(256) k_decode(const float* __restrict__ pred) {
    __shared__ float sp[128 * 85];
    const int nT = 600;
    const int b  = blockIdx.x / nT;
    const int t  = blockIdx.x % nT;
    const int a0 = t << 7;
    const int na = min(128, A_N - a0);

    // pure streaming copy: independent iterations -> deep MLP
    const float4* src4 = (const float4*)(pred + ((size_t)b * A_N + a0) * 84);
    const int tot4 = na * 21;
    for (int i = threadIdx.x; i < tot4; i += 256) {
        float4 v = src4[i];
        int la = i / 21;
        float* d = &sp[la * 85 + (i - la * 21) * 4];
        d[0] = v.x; d[1] = v.y; d[2] = v.z; d[3] = v.w;
    }
    __syncthreads();

    // scan smem for high logits; push (rare: ~2.3%)
    const int tot = na * 84;
    for (int i = threadIdx.x; i < tot; i += 256) {
        int la  = i / 84;
        int col = i - la * 84;
        if (col >= 4) {
            float x = sp[la * 85 + col];
            if (x > PUSH_T) {
                int c = col - 4;
                int a = a0 + la;
                int task = b * NCLS + c;
                float s = 1.0f / (1.0f + expf(-x));
                int idx = atomicAdd(&g_cnt[task], 1);
                if (idx < CCAP) {
                    unsigned key = __float_as_uint(s) | 0x80000000u;
                    g_cand[(size_t)task * CCAP + idx] =
                        ((unsigned long long)key << 32) | (unsigned)(~(unsigned)a);
                }
            }
        }
    }
}

// =====================================================================
// Kernel 2: per (b,c) exact top-256 + greedy NMS + per-class top-100
// =====================================================================
__global__ void __launch_bounds__(256) k_select(const float* __restrict__ pred,
                                                const float* __restrict__ anchors) {
    extern __shared__ unsigned char sm[];
    unsigned long long* CAND = (unsigned long long*)sm;            // 24576B
    unsigned*           hist = (unsigned*)(sm + 24576);            // 16384B
    unsigned long long* BUF  = (unsigned long long*)(sm + 40960);  // 8192B
    unsigned*           csum = (unsigned*)(sm + 49152);            // 1028B
    int*                ctrl = (int*)(sm + 50184);                 // 32B

    const int tid  = threadIdx.x;
    const int task = blockIdx.x;
    const int b    = task / NCLS;
    const int c    = task % NCLS;

    const int n = g_cnt[task];
    const bool fast = (n >= KPRE && n <= CCAP);

    for (int i = tid; i < NBIN; i += 256) hist[i] = 0;
    if (tid < 8) ctrl[tid] = 0;
    __syncthreads();

    if (fast) {
        for (int i = tid; i < n; i += 256) CAND[i] = g_cand[(size_t)task * CCAP + i];
        __syncthreads();
        for (int i = tid; i < n; i += 256)
            atomicAdd(&hist[(unsigned)(CAND[i] >> 52)], 1u);
        __syncthreads();
        (void)suffix_total<16>(hist, csum, tid);
        crossing<16>(hist, csum, ctrl, KPRE, tid);
        const unsigned B1 = (unsigned)ctrl[0];
        const unsigned C1 = (unsigned)ctrl[1];
        __syncthreads();

        for (int i = tid; i < NBIN; i += 256) hist[i] = 0;
        __syncthreads();
        for (int i = tid; i < n; i += 256) {
            unsigned long long e = CAND[i];
            if ((unsigned)(e >> 52) == B1) atomicAdd(&hist[(unsigned)(e >> 40) & 0xFFFu], 1u);
        }
        __syncthreads();
        (void)suffix_total<16>(hist, csum, tid);
        crossing<16>(hist, csum, ctrl, KPRE - C1, tid);
        const unsigned B2 = (unsigned)ctrl[0];
        if (tid == 0) ctrl[2] = 0;
        __syncthreads();

        for (int i = tid; i < n; i += 256) {
            unsigned long long e = CAND[i];
            unsigned t12 = (unsigned)(e >> 52);
            bool take = t12 > B1 || (t12 == B1 && ((unsigned)(e >> 40) & 0xFFFu) >= B2);
            if (take) {
                int p = atomicAdd(&ctrl[2], 1);
                if (p < BUFN) BUF[p] = e;
            }
        }
        __syncthreads();
    } else {
        // exact fallback: strided global rescan of this class column
        unsigned cnt = 0;
        for (int a = tid; a < A_N; a += 256) {
            float x = pred[((size_t)b * A_N + a) * 84 + 4 + c];
            float s = 1.0f / (1.0f + expf(-x));
            if (s > 0.05f) { ++cnt; atomicAdd(&hist[fkey32(s) >> 20], 1u); }
        }
        for (int o = 16; o; o >>= 1) cnt += __shfl_down_sync(0xFFFFFFFFu, cnt, o);
        if ((tid & 31) == 0) atomicAdd((unsigned*)&ctrl[5], cnt);
        __syncthreads();
        const unsigned total = (unsigned)ctrl[5];
        if (total == 0u) {
            for (int p = tid; p < MDPC; p += 256) {
                g_cls_scores[task * MDPC + p] = -1.0f;
                g_cls_boxes [task * MDPC + p] = make_float4(0.f, 0.f, 0.f, 0.f);
            }
            return;
        }
        const unsigned target = total < (unsigned)KPRE ? total : (unsigned)KPRE;
        (void)suffix_total<16>(hist, csum, tid);
        crossing<16>(hist, csum, ctrl, target, tid);
        const unsigned B1 = (unsigned)ctrl[0];
        const unsigned C1 = (unsigned)ctrl[1];
        __syncthreads();
        for (int i = tid; i < NBIN; i += 256) hist[i] = 0;
        __syncthreads();
        for (int a = tid; a < A_N; a += 256) {
            float x = pred[((size_t)b * A_N + a) * 84 + 4 + c];
            float s = 1.0f / (1.0f + expf(-x));
            if (s > 0.05f) {
                unsigned key = fkey32(s);
                if ((key >> 20) == B1) atomicAdd(&hist[(key >> 8) & 0xFFFu], 1u);
            }
        }
        __syncthreads();
        (void)suffix_total<16>(hist, csum, tid);
        crossing<16>(hist, csum, ctrl, target - C1, tid);
        const unsigned B2 = (unsigned)ctrl[0];
        if (tid == 0) ctrl[2] = 0;
        __syncthreads();
        for (int a = tid; a < A_N; a += 256) {
            float x = pred[((size_t)b * A_N + a) * 84 + 4 + c];
            float s = 1.0f / (1.0f + expf(-x));
            if (s > 0.05f) {
                unsigned key = fkey32(s);
                unsigned t12 = key >> 20;
                bool take = t12 > B1 || (t12 == B1 && ((key >> 8) & 0xFFFu) >= B2);
                if (take) {
                    int p = atomicAdd(&ctrl[2], 1);
                    if (p < BUFN)
                        BUF[p] = ((unsigned long long)key << 32) | (unsigned)(~(unsigned)a);
                }
            }
        }
        __syncthreads();
    }

    int sel = ctrl[2]; if (sel > BUFN) sel = BUFN;
    const int W = (sel <= 512) ? 512 : 1024;
    for (int i = sel + tid; i < W; i += 256) BUF[i] = 0ull;
    __syncthreads();

    for (int kk = 2; kk <= W; kk <<= 1) {
        for (int j = kk >> 1; j > 0; j >>= 1) {
            for (int i = tid; i < W; i += 256) {
                int ix = i ^ j;
                if (ix > i) {
                    unsigned long long x = BUF[i], y = BUF[ix];
                    bool sw = ((i & kk) == 0) ? (x < y) : (x > y);
                    if (sw) { BUF[i] = y; BUF[ix] = x; }
                }
            }
            __syncthreads();
        }
    }

    // ---- NMS on top-256 ----
    float*    X1    = (float*)sm;
    float*    Y1    = (float*)(sm + 1024);
    float*    X2    = (float*)(sm + 2048);
    float*    Y2    = (float*)(sm + 3072);
    float*    AR    = (float*)(sm + 4096);
    float*    SC    = (float*)(sm + 5120);
    unsigned* MASKS = (unsigned*)(sm + 6144);
    unsigned* KEEPW = (unsigned*)(sm + 14336);
    unsigned* WPFX  = (unsigned*)(sm + 14400);

    {
        unsigned long long e = BUF[tid];
        unsigned key  = (unsigned)(e >> 32);
        unsigned aidx = ~(unsigned)(e & 0xFFFFFFFFull);
        float  s  = -1.0f;
        float4 bx = make_float4(0.f, 0.f, 0.f, 0.f);
        if (key) {
            const float4 bp = *(const float4*)(pred + ((size_t)b * A_N + aidx) * 84);
            const float4 an = ((const float4*)anchors)[aidx];
            float cx = bp.x * 0.1f * an.z + an.x;
            float cy = bp.y * 0.1f * an.w + an.y;
            float w  = expf(bp.z * 0.2f) * an.z;
            float h  = expf(bp.w * 0.2f) * an.w;
            bx = make_float4(cx - w * 0.5f, cy - h * 0.5f, cx + w * 0.5f, cy + h * 0.5f);
            s  = __uint_as_float(key & 0x7FFFFFFFu);
        }
        X1[tid] = bx.x; Y1[tid] = bx.y; X2[tid] = bx.z; Y2[tid] = bx.w;
        AR[tid] = (bx.z - bx.x) * (bx.w - bx.y);
        SC[tid] = s;
        unsigned bal = __ballot_sync(0xFFFFFFFFu, key != 0u);
        if ((tid & 31) == 0) KEEPW[tid >> 5] = bal;
    }
    __syncthreads();

    {
        float ax1 = X1[tid], ay1 = Y1[tid], ax2 = X2[tid], ay2 = Y2[tid], aa = AR[tid];
        for (int w = 0; w < 8; ++w) {
            unsigned m = 0;
            for (int l = 0; l < 32; ++l) {
                int j = w * 32 + l;
                if (j > tid) {
                    float iw = fmaxf(fminf(ax2, X2[j]) - fmaxf(ax1, X1[j]), 0.f);
                    float ih = fmaxf(fminf(ay2, Y2[j]) - fmaxf(ay1, Y1[j]), 0.f);
                    float inter = iw * ih;
                    float iou = inter / fmaxf(aa + AR[j] - inter, 1e-8f);
                    if (iou > 0.5f) m |= (1u << l);
                }
            }
            MASKS[tid * 8 + w] = m;
        }
    }
    __syncthreads();

    if (tid < 32) {
        unsigned kw = (tid < 8) ? KEEPW[tid] : 0u;
        for (int i = 0; i < 256; ++i) {
            unsigned word = __shfl_sync(0xFFFFFFFFu, kw, i >> 5);
            if ((word >> (i & 31)) & 1u) {
                if (tid < 8) kw &= ~MASKS[i * 8 + tid];
            }
        }
        if (tid < 8) KEEPW[tid] = kw;
    }
    __syncthreads();

    if (tid == 0) {
        unsigned run = 0;
        for (int w = 0; w < 8; ++w) { WPFX[w] = run; run += __popc(KEEPW[w]); }
        WPFX[8] = run;
    }
    __syncthreads();

    {
        unsigned w = tid >> 5, bpos = tid & 31;
        unsigned kwv = KEEPW[w];
        bool kept = (kwv >> bpos) & 1u;
        unsigned p = WPFX[w] + __popc(kwv & ((1u << bpos) - 1u));
        if (kept && p < MDPC) {
            g_cls_scores[task * MDPC + p] = SC[tid];
            g_cls_boxes [task * MDPC + p] = make_float4(X1[tid], Y1[tid], X2[tid], Y2[tid]);
        }
        int kc = (int)WPFX[8];
        for (int q = kc + tid; q < MDPC; q += 256) {
            g_cls_scores[task * MDPC + q] = -1.0f;
            g_cls_boxes [task * MDPC + q] = make_float4(0.f, 0.f, 0.f, 0.f);
        }
    }
}

// =====================================================================
// Kernel 3: per image top-100 of 8000 (smem-staged)
// =====================================================================
__global__ void __launch_bounds__(256) k_final(float* __restrict__ out) {
    extern __shared__ unsigned char sm[];
    unsigned long long* ENT  = (unsigned long long*)sm;              // 65536B
    unsigned*           hist = (unsigned*)(sm + 65536);              // 16384B
    unsigned long long* BUF  = (unsigned long long*)(sm + 81920);    // 2048B
    unsigned*           csum = (unsigned*)(sm + 83968);              // 1028B
    int*                ctrl = (int*)(sm + 85000);                   // 32B

    const int tid = threadIdx.x;
    const int b   = blockIdx.x;
    const float4* sc4 = (const float4*)(g_cls_scores + b * NCLS * MDPC);

    for (int i = tid; i < NBIN; i += 256) hist[i] = 0;
    if (tid < 8) ctrl[tid] = 0;
    __syncthreads();

    // stage: unrolled float4 loads, build entries in smem
    unsigned cnt = 0;
#pragma unroll
    for (int r = 0; r < (NCLS * MDPC / 4 + 255) / 256; ++r) {
        int q = r * 256 + tid;
        if (q < NCLS * MDPC / 4) {
            float4 v = sc4[q];
            float xs[4] = { v.x, v.y, v.z, v.w };
#pragma unroll
            for (int j = 0; j < 4; ++j) {
                int i = q * 4 + j;
                unsigned long long e = 0ull;
                if (xs[j] > 0.0f) {
                    ++cnt;
                    e = ((unsigned long long)fkey32(xs[j]) << 32) | (unsigned)(~(unsigned)i);
                }
                ENT[i] = e;
            }
        }
    }
    for (int o = 16; o; o >>= 1) cnt += __shfl_down_sync(0xFFFFFFFFu, cnt, o);
    if ((tid & 31) == 0) atomicAdd((unsigned*)&ctrl[5], cnt);
    __syncthreads();
    const unsigned npos = (unsigned)ctrl[5];

    if (npos >= (unsigned)MAXD) {
        for (int i = tid; i < NCLS * MDPC; i += 256) {
            unsigned long long e = ENT[i];
            if (e) atomicAdd(&hist[(unsigned)(e >> 52)], 1u);
        }
        __syncthreads();
        (void)suffix_total<16>(hist, csum, tid);
        crossing<16>(hist, csum, ctrl, MAXD, tid);
        const unsigned B1 = (unsigned)ctrl[0];
        const unsigned C1 = (unsigned)ctrl[1];
        __syncthreads();
        for (int i = tid; i < NBIN; i += 256) hist[i] = 0;
        __syncthreads();
        for (int i = tid; i < NCLS * MDPC; i += 256) {
            unsigned long long e = ENT[i];
            if (e && (unsigned)(e >> 52) == B1) atomicAdd(&hist[(unsigned)(e >> 40) & 0xFFFu], 1u);
        }
        __syncthreads();
        (void)suffix_total<16>(hist, csum, tid);
        crossing<16>(hist, csum, ctrl, MAXD - C1, tid);
        const unsigned B2 = (unsigned)ctrl[0];
        if (tid == 0) ctrl[2] = 0;
        __syncthreads();
        for (int i = tid; i < NCLS * MDPC; i += 256) {
            unsigned long long e = ENT[i];
            if (!e) continue;
            unsigned t12 = (unsigned)(e >> 52);
            bool take = t12 > B1 || (t12 == B1 && ((unsigned)(e >> 40) & 0xFFFu) >= B2);
            if (take) {
                int p = atomicAdd(&ctrl[2], 1);
                if (p < 256) BUF[p] = e;
            }
        }
        __syncthreads();
    } else {
        if (tid == 0) ctrl[2] = 0;
        __syncthreads();
        for (int i = tid; i < NCLS * MDPC; i += 256) {
            unsigned long long e = ENT[i];
            if (e) {
                int p = atomicAdd(&ctrl[2], 1);
                if (p < 256) BUF[p] = e;
            }
        }
        __syncthreads();
    }

    int sel = ctrl[2]; if (sel > 256) sel = 256;
    if (tid >= sel) BUF[tid] = 0ull;
    __syncthreads();

    for (int kk = 2; kk <= 256; kk <<= 1) {
        for (int j = kk >> 1; j > 0; j >>= 1) {
            int ix = tid ^ j;
            if (ix > tid) {
                unsigned long long x = BUF[tid], y = BUF[ix];
                bool sw = ((tid & kk) == 0) ? (x < y) : (x > y);
                if (sw) { BUF[tid] = y; BUF[ix] = x; }
            }
            __syncthreads();
        }
    }

    __shared__ int vc;
    if (tid == 0) vc = 0;
    __syncthreads();

    if (tid < MAXD) {
        unsigned long long e = BUF[tid];
        unsigned key  = (unsigned)(e >> 32);
        unsigned flat = ~(unsigned)(e & 0xFFFFFFFFull);
        bool valid = (key != 0u);
        float4 bx = make_float4(0.f, 0.f, 0.f, 0.f);
        float cls = 0.0f, so = 0.0f;
        if (valid) {
            float s = __uint_as_float((key & 0x80000000u) ? (key & 0x7FFFFFFFu) : ~key);
            bx  = g_cls_boxes[b * NCLS * MDPC + flat];
            cls = (float)(flat / MDPC);
            so  = s;
            atomicAdd(&vc, 1);
        }
        out[b * 400 + tid * 4 + 0] = bx.x;
        out[b * 400 + tid * 4 + 1] = bx.y;
        out[b * 400 + tid * 4 + 2] = bx.z;
        out[b * 400 + tid * 4 + 3] = bx.w;
        out[NB * MAXD * 4 + b * MAXD + tid]             = so;
        out[NB * MAXD * 4 + NB * MAXD + b * MAXD + tid] = cls;
    }
    __syncthreads();
    if (tid == 0) out[NB * MAXD * 6 + b] = (float)vc;
}

// =====================================================================
extern "C" void kernel_launch(void* const* d_in, const int* in_sizes, int n_in,
                              void* d_out, int out_size) {
    (void)in_sizes; (void)n_in; (void)out_size;
    const float* pred    = (const float*)d_in[1];
    const float* anchors = (const float*)d_in[2];
    float* out = (float*)d_out;

    k_zero<<<3, 256>>>();
    k_decode<<<NB * 600, 256>>>(pred);

    cudaFuncSetAttribute(k_select, cudaFuncAttributeMaxDynamicSharedMemorySize, 50216);
    k_select<<<NTASK, 256, 50216>>>(pred, anchors);

    cudaFuncSetAttribute(k_final, cudaFuncAttributeMaxDynamicSharedMemorySize, 85032);
    k_final<<<NB, 256, 85032>>>(out);
}

// round 6
// speedup vs baseline: 1.9771x; 1.9771x over previous
#include <cuda_runtime.h>
#include <math.h>

#define A_N    76725
#define NCLS   80
#define NB     8
#define NTASK  (NB*NCLS)
#define KPRE   256
#define MDPC   100
#define MAXD   100
#define CCAP   3072
#define BUFN   1024
#define NBIN   4096
#define PUSH_T 2.0f
#define CNTSTR 32            // counter stride (ints) -> 128B apart

__device__ unsigned long long g_cand[(size_t)NTASK * CCAP];
__device__ int    g_cnt[NTASK * CNTSTR];
__device__ float  g_cls_scores[NTASK * MDPC];
__device__ float4 g_cls_boxes[NTASK * MDPC];

__device__ __forceinline__ unsigned fkey32(float x) {
    unsigned b = __float_as_uint(x);
    return (b & 0x80000000u) ? ~b : (b | 0x80000000u);
}

template <int BPT>
__device__ __forceinline__ unsigned suffix_total(const unsigned* hist, unsigned* csum, int tid) {
    unsigned s = 0;
    const int base = tid * BPT;
#pragma unroll
    for (int r = 0; r < BPT; ++r) s += hist[base + r];
    csum[tid] = s;
    __syncthreads();
    for (int off = 1; off < 256; off <<= 1) {
        unsigned add = (tid + off < 256) ? csum[tid + off] : 0u;
        __syncthreads();
        csum[tid] += add;
        __syncthreads();
    }
    return csum[0];
}

template <int BPT>
__device__ __forceinline__ void crossing(const unsigned* hist, const unsigned* csum, int* ctrl,
                                         unsigned target, int tid) {
    unsigned run = (tid + 1 < 256) ? csum[tid + 1] : 0u;
    const int base = tid * BPT;
    for (int i = base + BPT - 1; i >= base; --i) {
        unsigned h = hist[i];
        run += h;
        if (run >= target && run - h < target) { ctrl[0] = i; ctrl[1] = (int)(run - h); }
    }
    __syncthreads();
}

// =====================================================================
__global__ void k_nop() {}   // positions the ncu capture window

__global__ void k_zero() {
    int i = blockIdx.x * 256 + threadIdx.x;
    if (i < NTASK * CNTSTR) g_cnt[i] = 0;
}

// =====================================================================
// Kernel 1: stream predictions, push high-logit candidates (R4 fused form)
// =====================================================================
__global__ void __launch_bounds__(256) k_decode(const float* __restrict__ pred) {
    const int nT = 600;
    const int b  = blockIdx.x / nT;
    const int t  = blockIdx.x % nT;
    const int a0 = t << 7;
    const int na = min(128, A_N - a0);
    const float4* src = (const float4*)(pred + ((size_t)b * A_N + a0) * 84);
    const int tot = na * 21;

    for (int i = threadIdx.x; i < tot; i += 256) {
        float4 v = src[i];
        int la   = i / 21;
        int col0 = (i - la * 21) * 4;
        int a    = a0 + la;
        float xs[4] = { v.x, v.y, v.z, v.w };
#pragma unroll
        for (int j = 0; j < 4; ++j) {
            float x = xs[j];
            int col = col0 + j;
            if (col >= 4 && x > PUSH_T) {
                int c = col - 4;
                int task = b * NCLS + c;
                float s = 1.0f / (1.0f + expf(-x));
                int idx = atomicAdd(&g_cnt[task * CNTSTR], 1);
                if (idx < CCAP) {
                    unsigned key = __float_as_uint(s) | 0x80000000u;
                    g_cand[(size_t)task * CCAP + idx] =
                        ((unsigned long long)key << 32) | (unsigned)(~(unsigned)a);
                }
            }
        }
    }
}

// =====================================================================
// Kernel 2: per (b,c) exact top-256 + greedy NMS + per-class top-100
// =====================================================================
__global__ void __launch_bounds__(256) k_select(const float* __restrict__ pred,
                                                const float* __restrict__ anchors) {
    extern __shared__ unsigned char sm[];
    unsigned long long* CAND = (unsigned long long*)sm;            // 24576B
    unsigned*           hist = (unsigned*)(sm + 24576);            // 16384B
    unsigned long long* BUF  = (unsigned long long*)(sm + 40960);  // 8192B
    unsigned*           csum = (unsigned*)(sm + 49152);            // 1028B
    int*                ctrl = (int*)(sm + 50184);                 // 32B

    const int tid  = threadIdx.x;
    const int task = blockIdx.x;
    const int b    = task / NCLS;
    const int c    = task % NCLS;

    const int n = g_cnt[task * CNTSTR];
    const bool fast = (n >= KPRE && n <= CCAP);

    for (int i = tid; i < NBIN; i += 256) hist[i] = 0;
    if (tid < 8) ctrl[tid] = 0;
    __syncthreads();

    if (fast) {
        for (int i = tid; i < n; i += 256) CAND[i] = g_cand[(size_t)task * CCAP + i];
        __syncthreads();
        for (int i = tid; i < n; i += 256)
            atomicAdd(&hist[(unsigned)(CAND[i] >> 52)], 1u);
        __syncthreads();
        (void)suffix_total<16>(hist, csum, tid);
        crossing<16>(hist, csum, ctrl, KPRE, tid);
        const unsigned B1 = (unsigned)ctrl[0];
        const unsigned C1 = (unsigned)ctrl[1];
        __syncthreads();

        for (int i = tid; i < NBIN; i += 256) hist[i] = 0;
        __syncthreads();
        for (int i = tid; i < n; i += 256) {
            unsigned long long e = CAND[i];
            if ((unsigned)(e >> 52) == B1) atomicAdd(&hist[(unsigned)(e >> 40) & 0xFFFu], 1u);
        }
        __syncthreads();
        (void)suffix_total<16>(hist, csum, tid);
        crossing<16>(hist, csum, ctrl, KPRE - C1, tid);
        const unsigned B2 = (unsigned)ctrl[0];
        if (tid == 0) ctrl[2] = 0;
        __syncthreads();

        for (int i = tid; i < n; i += 256) {
            unsigned long long e = CAND[i];
            unsigned t12 = (unsigned)(e >> 52);
            bool take = t12 > B1 || (t12 == B1 && ((unsigned)(e >> 40) & 0xFFFu) >= B2);
            if (take) {
                int p = atomicAdd(&ctrl[2], 1);
                if (p < BUFN) BUF[p] = e;
            }
        }
        __syncthreads();
    } else {
        unsigned cnt = 0;
        for (int a = tid; a < A_N; a += 256) {
            float x = pred[((size_t)b * A_N + a) * 84 + 4 + c];
            float s = 1.0f / (1.0f + expf(-x));
            if (s > 0.05f) { ++cnt; atomicAdd(&hist[fkey32(s) >> 20], 1u); }
        }
        for (int o = 16; o; o >>= 1) cnt += __shfl_down_sync(0xFFFFFFFFu, cnt, o);
        if ((tid & 31) == 0) atomicAdd((unsigned*)&ctrl[5], cnt);
        __syncthreads();
        const unsigned total = (unsigned)ctrl[5];
        if (total == 0u) {
            for (int p = tid; p < MDPC; p += 256) {
                g_cls_scores[task * MDPC + p] = -1.0f;
                g_cls_boxes [task * MDPC + p] = make_float4(0.f, 0.f, 0.f, 0.f);
            }
            return;
        }
        const unsigned target = total < (unsigned)KPRE ? total : (unsigned)KPRE;
        (void)suffix_total<16>(hist, csum, tid);
        crossing<16>(hist, csum, ctrl, target, tid);
        const unsigned B1 = (unsigned)ctrl[0];
        const unsigned C1 = (unsigned)ctrl[1];
        __syncthreads();
        for (int i = tid; i < NBIN; i += 256) hist[i] = 0;
        __syncthreads();
        for (int a = tid; a < A_N; a += 256) {
            float x = pred[((size_t)b * A_N + a) * 84 + 4 + c];
            float s = 1.0f / (1.0f + expf(-x));
            if (s > 0.05f) {
                unsigned key = fkey32(s);
                if ((key >> 20) == B1) atomicAdd(&hist[(key >> 8) & 0xFFFu], 1u);
            }
        }
        __syncthreads();
        (void)suffix_total<16>(hist, csum, tid);
        crossing<16>(hist, csum, ctrl, target - C1, tid);
        const unsigned B2 = (unsigned)ctrl[0];
        if (tid == 0) ctrl[2] = 0;
        __syncthreads();
        for (int a = tid; a < A_N; a += 256) {
            float x = pred[((size_t)b * A_N + a) * 84 + 4 + c];
            float s = 1.0f / (1.0f + expf(-x));
            if (s > 0.05f) {
                unsigned key = fkey32(s);
                unsigned t12 = key >> 20;
                bool take = t12 > B1 || (t12 == B1 && ((key >> 8) & 0xFFFu) >= B2);
                if (take) {
                    int p = atomicAdd(&ctrl[2], 1);
                    if (p < BUFN)
                        BUF[p] = ((unsigned long long)key << 32) | (unsigned)(~(unsigned)a);
                }
            }
        }
        __syncthreads();
    }

    int sel = ctrl[2]; if (sel > BUFN) sel = BUFN;
    const int W = (sel <= 512) ? 512 : 1024;
    for (int i = sel + tid; i < W; i += 256) BUF[i] = 0ull;
    __syncthreads();

    for (int kk = 2; kk <= W; kk <<= 1) {
        for (int j = kk >> 1; j > 0; j >>= 1) {
            for (int i = tid; i < W; i += 256) {
                int ix = i ^ j;
                if (ix > i) {
                    unsigned long long x = BUF[i], y = BUF[ix];
                    bool sw = ((i & kk) == 0) ? (x < y) : (x > y);
                    if (sw) { BUF[i] = y; BUF[ix] = x; }
                }
            }
            __syncthreads();
        }
    }

    // ---- NMS on top-256 ----
    float*    X1    = (float*)sm;
    float*    Y1    = (float*)(sm + 1024);
    float*    X2    = (float*)(sm + 2048);
    float*    Y2    = (float*)(sm + 3072);
    float*    AR    = (float*)(sm + 4096);
    float*    SC    = (float*)(sm + 5120);
    unsigned* MASKS = (unsigned*)(sm + 6144);
    unsigned* KEEPW = (unsigned*)(sm + 14336);
    unsigned* WPFX  = (unsigned*)(sm + 14400);

    {
        unsigned long long e = BUF[tid];
        unsigned key  = (unsigned)(e >> 32);
        unsigned aidx = ~(unsigned)(e & 0xFFFFFFFFull);
        float  s  = -1.0f;
        float4 bx = make_float4(0.f, 0.f, 0.f, 0.f);
        if (key) {
            const float4 bp = *(const float4*)(pred + ((size_t)b * A_N + aidx) * 84);
            const float4 an = ((const float4*)anchors)[aidx];
            float cx = bp.x * 0.1f * an.z + an.x;
            float cy = bp.y * 0.1f * an.w + an.y;
            float w  = expf(bp.z * 0.2f) * an.z;
            float h  = expf(bp.w * 0.2f) * an.w;
            bx = make_float4(cx - w * 0.5f, cy - h * 0.5f, cx + w * 0.5f, cy + h * 0.5f);
            s  = __uint_as_float(key & 0x7FFFFFFFu);
        }
        X1[tid] = bx.x; Y1[tid] = bx.y; X2[tid] = bx.z; Y2[tid] = bx.w;
        AR[tid] = (bx.z - bx.x) * (bx.w - bx.y);
        SC[tid] = s;
        unsigned bal = __ballot_sync(0xFFFFFFFFu, key != 0u);
        if ((tid & 31) == 0) KEEPW[tid >> 5] = bal;
    }
    __syncthreads();

    {
        float ax1 = X1[tid], ay1 = Y1[tid], ax2 = X2[tid], ay2 = Y2[tid], aa = AR[tid];
        for (int w = 0; w < 8; ++w) {
            unsigned m = 0;
            for (int l = 0; l < 32; ++l) {
                int j = w * 32 + l;
                if (j > tid) {
                    float iw = fmaxf(fminf(ax2, X2[j]) - fmaxf(ax1, X1[j]), 0.f);
                    float ih = fmaxf(fminf(ay2, Y2[j]) - fmaxf(ay1, Y1[j]), 0.f);
                    float inter = iw * ih;
                    float iou = inter / fmaxf(aa + AR[j] - inter, 1e-8f);
                    if (iou > 0.5f) m |= (1u << l);
                }
            }
            MASKS[tid * 8 + w] = m;
        }
    }
    __syncthreads();

    if (tid < 32) {
        unsigned kw = (tid < 8) ? KEEPW[tid] : 0u;
        for (int i = 0; i < 256; ++i) {
            unsigned word = __shfl_sync(0xFFFFFFFFu, kw, i >> 5);
            if ((word >> (i & 31)) & 1u) {
                if (tid < 8) kw &= ~MASKS[i * 8 + tid];
            }
        }
        if (tid < 8) KEEPW[tid] = kw;
    }
    __syncthreads();

    if (tid == 0) {
        unsigned run = 0;
        for (int w = 0; w < 8; ++w) { WPFX[w] = run; run += __popc(KEEPW[w]); }
        WPFX[8] = run;
    }
    __syncthreads();

    {
        unsigned w = tid >> 5, bpos = tid & 31;
        unsigned kwv = KEEPW[w];
        bool kept = (kwv >> bpos) & 1u;
        unsigned p = WPFX[w] + __popc(kwv & ((1u << bpos) - 1u));
        if (kept && p < MDPC) {
            g_cls_scores[task * MDPC + p] = SC[tid];
            g_cls_boxes [task * MDPC + p] = make_float4(X1[tid], Y1[tid], X2[tid], Y2[tid]);
        }
        int kc = (int)WPFX[8];
        for (int q = kc + tid; q < MDPC; q += 256) {
            g_cls_scores[task * MDPC + q] = -1.0f;
            g_cls_boxes [task * MDPC + q] = make_float4(0.f, 0.f, 0.f, 0.f);
        }
    }
}

// =====================================================================
// Kernel 3: per image top-100 of 8000
// =====================================================================
__global__ void __launch_bounds__(256) k_final(float* __restrict__ out) {
    __shared__ unsigned hist[NBIN];
    __shared__ unsigned long long BUF[256];
    __shared__ unsigned csum[257];
    __shared__ int ctrl[8];
    __shared__ int vc;

    const int tid = threadIdx.x;
    const int b   = blockIdx.x;
    const float* sc = g_cls_scores + b * NCLS * MDPC;

    for (int i = tid; i < NBIN; i += 256) hist[i] = 0;
    if (tid < 8) ctrl[tid] = 0;
    __syncthreads();

    unsigned cnt = 0;
    for (int i = tid; i < NCLS * MDPC; i += 256) {
        float s = sc[i];
        if (s > 0.0f) { ++cnt; atomicAdd(&hist[fkey32(s) >> 20], 1u); }
    }
    for (int o = 16; o; o >>= 1) cnt += __shfl_down_sync(0xFFFFFFFFu, cnt, o);
    if ((tid & 31) == 0) atomicAdd((unsigned*)&ctrl[5], cnt);
    __syncthreads();
    const unsigned npos = (unsigned)ctrl[5];

    if (npos >= (unsigned)MAXD) {
        (void)suffix_total<16>(hist, csum, tid);
        crossing<16>(hist, csum, ctrl, MAXD, tid);
        const unsigned B1 = (unsigned)ctrl[0];
        const unsigned C1 = (unsigned)ctrl[1];
        __syncthreads();
        for (int i = tid; i < NBIN; i += 256) hist[i] = 0;
        __syncthreads();
        for (int i = tid; i < NCLS * MDPC; i += 256) {
            float s = sc[i];
            if (s > 0.0f) {
                unsigned key = fkey32(s);
                if ((key >> 20) == B1) atomicAdd(&hist[(key >> 8) & 0xFFFu], 1u);
            }
        }
        __syncthreads();
        (void)suffix_total<16>(hist, csum, tid);
        crossing<16>(hist, csum, ctrl, MAXD - C1, tid);
        const unsigned B2 = (unsigned)ctrl[0];
        if (tid == 0) ctrl[2] = 0;
        __syncthreads();
        for (int i = tid; i < NCLS * MDPC; i += 256) {
            float s = sc[i];
            if (s > 0.0f) {
                unsigned key = fkey32(s);
                unsigned t12 = key >> 20;
                bool take = t12 > B1 || (t12 == B1 && ((key >> 8) & 0xFFFu) >= B2);
                if (take) {
                    int p = atomicAdd(&ctrl[2], 1);
                    if (p < 256)
                        BUF[p] = ((unsigned long long)key << 32) | (unsigned)(~(unsigned)i);
                }
            }
        }
        __syncthreads();
    } else {
        if (tid == 0) ctrl[2] = 0;
        __syncthreads();
        for (int i = tid; i < NCLS * MDPC; i += 256) {
            float s = sc[i];
            if (s > 0.0f) {
                int p = atomicAdd(&ctrl[2], 1);
                if (p < 256)
                    BUF[p] = ((unsigned long long)fkey32(s) << 32) | (unsigned)(~(unsigned)i);
            }
        }
        __syncthreads();
    }

    int sel = ctrl[2]; if (sel > 256) sel = 256;
    if (tid >= sel) BUF[tid] = 0ull;
    __syncthreads();

    for (int kk = 2; kk <= 256; kk <<= 1) {
        for (int j = kk >> 1; j > 0; j >>= 1) {
            int ix = tid ^ j;
            if (ix > tid) {
                unsigned long long x = BUF[tid], y = BUF[ix];
                bool sw = ((tid & kk) == 0) ? (x < y) : (x > y);
                if (sw) { BUF[tid] = y; BUF[ix] = x; }
            }
            __syncthreads();
        }
    }

    if (tid == 0) vc = 0;
    __syncthreads();

    if (tid < MAXD) {
        unsigned long long e = BUF[tid];
        unsigned key  = (unsigned)(e >> 32);
        unsigned flat = ~(unsigned)(e & 0xFFFFFFFFull);
        bool valid = (key != 0u);
        float4 bx = make_float4(0.f, 0.f, 0.f, 0.f);
        float cls = 0.0f, so = 0.0f;
        if (valid) {
            float s = __uint_as_float((key & 0x80000000u) ? (key & 0x7FFFFFFFu) : ~key);
            bx  = g_cls_boxes[b * NCLS * MDPC + flat];
            cls = (float)(flat / MDPC);
            so  = s;
            atomicAdd(&vc, 1);
        }
        out[b * 400 + tid * 4 + 0] = bx.x;
        out[b * 400 + tid * 4 + 1] = bx.y;
        out[b * 400 + tid * 4 + 2] = bx.z;
        out[b * 400 + tid * 4 + 3] = bx.w;
        out[NB * MAXD * 4 + b * MAXD + tid]             = so;
        out[NB * MAXD * 4 + NB * MAXD + b * MAXD + tid] = cls;
    }
    __syncthreads();
    if (tid == 0) out[NB * MAXD * 6 + b] = (float)vc;
}

// =====================================================================
extern "C" void kernel_launch(void* const* d_in, const int* in_sizes, int n_in,
                              void* d_out, int out_size) {
    (void)in_sizes; (void)n_in; (void)out_size;
    const float* pred    = (const float*)d_in[1];
    const float* anchors = (const float*)d_in[2];
    float* out = (float*)d_out;

    k_nop<<<1, 32>>>();                      // shifts ncu capture onto k_select
    k_zero<<<80, 256>>>();
    k_decode<<<NB * 600, 256>>>(pred);

    cudaFuncSetAttribute(k_select, cudaFuncAttributeMaxDynamicSharedMemorySize, 50216);
    k_select<<<NTASK, 256, 50216>>>(pred, anchors);

    k_final<<<NB, 256>>>(out);
}

// round 7
// speedup vs baseline: 2.5224x; 1.2758x over previous
#include <cuda_runtime.h>
#include <math.h>

#define A_N    76725
#define NCLS   80
#define NB     8
#define NTASK  (NB*NCLS)
#define KPRE   256
#define MDPC   100
#define MAXD   100
#define CCAP   3072
#define BUFN   1024
#define NBIN2  2048          // k_select histogram bins
#define NBINF  4096          // k_final histogram bins
#define PUSH_T 2.0f
#define CNTSTR 32            // counter stride (ints) -> 128B apart

__device__ unsigned long long g_cand[(size_t)NTASK * CCAP];
__device__ int    g_cnt[NTASK * CNTSTR];
__device__ float  g_cls_scores[NTASK * MDPC];
__device__ float4 g_cls_boxes[NTASK * MDPC];

__device__ __forceinline__ unsigned fkey32(float x) {
    unsigned b = __float_as_uint(x);
    return (b & 0x80000000u) ? ~b : (b | 0x80000000u);
}

template <int BPT>
__device__ __forceinline__ unsigned suffix_total(const unsigned* hist, unsigned* csum, int tid) {
    unsigned s = 0;
    const int base = tid * BPT;
#pragma unroll
    for (int r = 0; r < BPT; ++r) s += hist[base + r];
    csum[tid] = s;
    __syncthreads();
    for (int off = 1; off < 256; off <<= 1) {
        unsigned add = (tid + off < 256) ? csum[tid + off] : 0u;
        __syncthreads();
        csum[tid] += add;
        __syncthreads();
    }
    return csum[0];
}

template <int BPT>
__device__ __forceinline__ void crossing(const unsigned* hist, const unsigned* csum, int* ctrl,
                                         unsigned target, int tid) {
    unsigned run = (tid + 1 < 256) ? csum[tid + 1] : 0u;
    const int base = tid * BPT;
    for (int i = base + BPT - 1; i >= base; --i) {
        unsigned h = hist[i];
        run += h;
        if (run >= target && run - h < target) { ctrl[0] = i; ctrl[1] = (int)(run - h); }
    }
    __syncthreads();
}

// =====================================================================
__global__ void k_nop() {}   // positions the ncu capture window on k_select

__global__ void k_zero() {
    int i = blockIdx.x * 256 + threadIdx.x;
    if (i < NTASK * CNTSTR) g_cnt[i] = 0;
}

// =====================================================================
// Kernel 1: stream predictions, push high-logit candidates
// =====================================================================
__global__ void __launch_bounds__(256) k_decode(const float* __restrict__ pred) {
    const int nT = 600;
    const int b  = blockIdx.x / nT;
    const int t  = blockIdx.x % nT;
    const int a0 = t << 7;
    const int na = min(128, A_N - a0);
    const float4* src = (const float4*)(pred + ((size_t)b * A_N + a0) * 84);
    const int tot = na * 21;

    for (int i = threadIdx.x; i < tot; i += 256) {
        float4 v = src[i];
        int la   = i / 21;
        int col0 = (i - la * 21) * 4;
        int a    = a0 + la;
        float xs[4] = { v.x, v.y, v.z, v.w };
#pragma unroll
        for (int j = 0; j < 4; ++j) {
            float x = xs[j];
            int col = col0 + j;
            if (col >= 4 && x > PUSH_T) {
                int c = col - 4;
                int task = b * NCLS + c;
                float s = 1.0f / (1.0f + expf(-x));
                int idx = atomicAdd(&g_cnt[task * CNTSTR], 1);
                if (idx < CCAP) {
                    unsigned key = __float_as_uint(s) | 0x80000000u;
                    g_cand[(size_t)task * CCAP + idx] =
                        ((unsigned long long)key << 32) | (unsigned)(~(unsigned)a);
                }
            }
        }
    }
}

// =====================================================================
// Kernel 2: per (b,c) exact top-256 + greedy NMS + per-class top-100
// smem layout (18KB total):
//   [0,8192)      hist (2048 u32)      | NMS: X1..SC [0,6144), MASKS [6144,14336)
//   [8192,9220)   csum (257 u32)       |      KEEPW [14336,14400), WPFX [14400,14440)
//   [9232,9264)   ctrl (8 int)
//   [9728,17920)  BUF (1024 u64)
// =====================================================================
__global__ void __launch_bounds__(256, 6) k_select(const float* __restrict__ pred,
                                                   const float* __restrict__ anchors) {
    extern __shared__ unsigned char sm[];
    unsigned*           hist = (unsigned*)sm;
    unsigned*           csum = (unsigned*)(sm + 8192);
    int*                ctrl = (int*)(sm + 9232);
    unsigned long long* BUF  = (unsigned long long*)(sm + 9728);

    const int tid  = threadIdx.x;
    const int task = blockIdx.x;
    const int b    = task / NCLS;
    const int c    = task % NCLS;

    const int n = g_cnt[task * CNTSTR];
    const bool fast = (n >= KPRE && n <= CCAP);
    const unsigned long long* cand = g_cand + (size_t)task * CCAP;

    for (int i = tid; i < NBIN2; i += 256) hist[i] = 0;
    if (tid < 8) ctrl[tid] = 0;
    __syncthreads();

    if (fast) {
        // level 1: bins = key bits [21:32)
        for (int i = tid; i < n; i += 256)
            atomicAdd(&hist[(unsigned)(cand[i] >> 53)], 1u);
        __syncthreads();
        (void)suffix_total<8>(hist, csum, tid);
        crossing<8>(hist, csum, ctrl, KPRE, tid);
        const unsigned B1 = (unsigned)ctrl[0];
        const unsigned C1 = (unsigned)ctrl[1];
        __syncthreads();

        // level 2: within B1, bins = key bits [10:21)
        for (int i = tid; i < NBIN2; i += 256) hist[i] = 0;
        __syncthreads();
        for (int i = tid; i < n; i += 256) {
            unsigned long long e = cand[i];
            if ((unsigned)(e >> 53) == B1) atomicAdd(&hist[(unsigned)(e >> 42) & 0x7FFu], 1u);
        }
        __syncthreads();
        (void)suffix_total<8>(hist, csum, tid);
        crossing<8>(hist, csum, ctrl, KPRE - C1, tid);
        const unsigned B2 = (unsigned)ctrl[0];
        if (tid == 0) ctrl[2] = 0;
        __syncthreads();

        for (int i = tid; i < n; i += 256) {
            unsigned long long e = cand[i];
            unsigned l1 = (unsigned)(e >> 53);
            bool take = l1 > B1 || (l1 == B1 && ((unsigned)(e >> 42) & 0x7FFu) >= B2);
            if (take) {
                int p = atomicAdd(&ctrl[2], 1);
                if (p < BUFN) BUF[p] = e;
            }
        }
        __syncthreads();
    } else {
        // exact fallback: strided global rescan of this class column
        unsigned cnt = 0;
        for (int a = tid; a < A_N; a += 256) {
            float x = pred[((size_t)b * A_N + a) * 84 + 4 + c];
            float s = 1.0f / (1.0f + expf(-x));
            if (s > 0.05f) { ++cnt; atomicAdd(&hist[fkey32(s) >> 21], 1u); }
        }
        for (int o = 16; o; o >>= 1) cnt += __shfl_down_sync(0xFFFFFFFFu, cnt, o);
        if ((tid & 31) == 0) atomicAdd((unsigned*)&ctrl[5], cnt);
        __syncthreads();
        const unsigned total = (unsigned)ctrl[5];
        if (total == 0u) {
            for (int p = tid; p < MDPC; p += 256) {
                g_cls_scores[task * MDPC + p] = -1.0f;
                g_cls_boxes [task * MDPC + p] = make_float4(0.f, 0.f, 0.f, 0.f);
            }
            return;
        }
        const unsigned target = total < (unsigned)KPRE ? total : (unsigned)KPRE;
        (void)suffix_total<8>(hist, csum, tid);
        crossing<8>(hist, csum, ctrl, target, tid);
        const unsigned B1 = (unsigned)ctrl[0];
        const unsigned C1 = (unsigned)ctrl[1];
        __syncthreads();
        for (int i = tid; i < NBIN2; i += 256) hist[i] = 0;
        __syncthreads();
        for (int a = tid; a < A_N; a += 256) {
            float x = pred[((size_t)b * A_N + a) * 84 + 4 + c];
            float s = 1.0f / (1.0f + expf(-x));
            if (s > 0.05f) {
                unsigned key = fkey32(s);
                if ((key >> 21) == B1) atomicAdd(&hist[(key >> 10) & 0x7FFu], 1u);
            }
        }
        __syncthreads();
        (void)suffix_total<8>(hist, csum, tid);
        crossing<8>(hist, csum, ctrl, target - C1, tid);
        const unsigned B2 = (unsigned)ctrl[0];
        if (tid == 0) ctrl[2] = 0;
        __syncthreads();
        for (int a = tid; a < A_N; a += 256) {
            float x = pred[((size_t)b * A_N + a) * 84 + 4 + c];
            float s = 1.0f / (1.0f + expf(-x));
            if (s > 0.05f) {
                unsigned key = fkey32(s);
                unsigned l1 = key >> 21;
                bool take = l1 > B1 || (l1 == B1 && ((key >> 10) & 0x7FFu) >= B2);
                if (take) {
                    int p = atomicAdd(&ctrl[2], 1);
                    if (p < BUFN)
                        BUF[p] = ((unsigned long long)key << 32) | (unsigned)(~(unsigned)a);
                }
            }
        }
        __syncthreads();
    }

    int sel = ctrl[2]; if (sel > BUFN) sel = BUFN;
    const int W = (sel <= 512) ? 512 : 1024;
    for (int i = sel + tid; i < W; i += 256) BUF[i] = 0ull;
    __syncthreads();

    for (int kk = 2; kk <= W; kk <<= 1) {
        for (int j = kk >> 1; j > 0; j >>= 1) {
            for (int i = tid; i < W; i += 256) {
                int ix = i ^ j;
                if (ix > i) {
                    unsigned long long x = BUF[i], y = BUF[ix];
                    bool sw = ((i & kk) == 0) ? (x < y) : (x > y);
                    if (sw) { BUF[i] = y; BUF[ix] = x; }
                }
            }
            __syncthreads();
        }
    }

    // ---- NMS on top-256 (aliases hist/csum/ctrl region; BUF read once) ----
    float*    X1    = (float*)sm;
    float*    Y1    = (float*)(sm + 1024);
    float*    X2    = (float*)(sm + 2048);
    float*    Y2    = (float*)(sm + 3072);
    float*    AR    = (float*)(sm + 4096);
    float*    SC    = (float*)(sm + 5120);
    unsigned* MASKS = (unsigned*)(sm + 6144);    // [256][8] = 8KB
    unsigned* KEEPW = (unsigned*)(sm + 14336);
    unsigned* WPFX  = (unsigned*)(sm + 14400);

    {
        unsigned long long e = BUF[tid];
        unsigned key  = (unsigned)(e >> 32);
        unsigned aidx = ~(unsigned)(e & 0xFFFFFFFFull);
        float  s  = -1.0f;
        float4 bx = make_float4(0.f, 0.f, 0.f, 0.f);
        if (key) {
            const float4 bp = *(const float4*)(pred + ((size_t)b * A_N + aidx) * 84);
            const float4 an = ((const float4*)anchors)[aidx];
            float cx = bp.x * 0.1f * an.z + an.x;
            float cy = bp.y * 0.1f * an.w + an.y;
            float w  = expf(bp.z * 0.2f) * an.z;
            float h  = expf(bp.w * 0.2f) * an.w;
            bx = make_float4(cx - w * 0.5f, cy - h * 0.5f, cx + w * 0.5f, cy + h * 0.5f);
            s  = __uint_as_float(key & 0x7FFFFFFFu);
        }
        X1[tid] = bx.x; Y1[tid] = bx.y; X2[tid] = bx.z; Y2[tid] = bx.w;
        AR[tid] = (bx.z - bx.x) * (bx.w - bx.y);
        SC[tid] = s;
        unsigned bal = __ballot_sync(0xFFFFFFFFu, key != 0u);
        if ((tid & 31) == 0) KEEPW[tid >> 5] = bal;
    }
    __syncthreads();

    {
        float ax1 = X1[tid], ay1 = Y1[tid], ax2 = X2[tid], ay2 = Y2[tid], aa = AR[tid];
        for (int w = 0; w < 8; ++w) {
            unsigned m = 0;
            for (int l = 0; l < 32; ++l) {
                int j = w * 32 + l;
                if (j > tid) {
                    float iw = fmaxf(fminf(ax2, X2[j]) - fmaxf(ax1, X1[j]), 0.f);
                    float ih = fmaxf(fminf(ay2, Y2[j]) - fmaxf(ay1, Y1[j]), 0.f);
                    float inter = iw * ih;
                    float iou = inter / fmaxf(aa + AR[j] - inter, 1e-8f);
                    if (iou > 0.5f) m |= (1u << l);
                }
            }
            MASKS[tid * 8 + w] = m;
        }
    }
    __syncthreads();

    if (tid < 32) {
        unsigned kw = (tid < 8) ? KEEPW[tid] : 0u;
        for (int i = 0; i < 256; ++i) {
            unsigned word = __shfl_sync(0xFFFFFFFFu, kw, i >> 5);
            if ((word >> (i & 31)) & 1u) {
                if (tid < 8) kw &= ~MASKS[i * 8 + tid];
            }
        }
        if (tid < 8) KEEPW[tid] = kw;
    }
    __syncthreads();

    if (tid == 0) {
        unsigned run = 0;
        for (int w = 0; w < 8; ++w) { WPFX[w] = run; run += __popc(KEEPW[w]); }
        WPFX[8] = run;
    }
    __syncthreads();

    {
        unsigned w = tid >> 5, bpos = tid & 31;
        unsigned kwv = KEEPW[w];
        bool kept = (kwv >> bpos) & 1u;
        unsigned p = WPFX[w] + __popc(kwv & ((1u << bpos) - 1u));
        if (kept && p < MDPC) {
            g_cls_scores[task * MDPC + p] = SC[tid];
            g_cls_boxes [task * MDPC + p] = make_float4(X1[tid], Y1[tid], X2[tid], Y2[tid]);
        }
        int kc = (int)WPFX[8];
        for (int q = kc + tid; q < MDPC; q += 256) {
            g_cls_scores[task * MDPC + q] = -1.0f;
            g_cls_boxes [task * MDPC + q] = make_float4(0.f, 0.f, 0.f, 0.f);
        }
    }
}

// =====================================================================
// Kernel 3: per image top-100 of 8000
// =====================================================================
__global__ void __launch_bounds__(256) k_final(float* __restrict__ out) {
    __shared__ unsigned hist[NBINF];
    __shared__ unsigned long long BUF[256];
    __shared__ unsigned csum[257];
    __shared__ int ctrl[8];
    __shared__ int vc;

    const int tid = threadIdx.x;
    const int b   = blockIdx.x;
    const float* sc = g_cls_scores + b * NCLS * MDPC;

    for (int i = tid; i < NBINF; i += 256) hist[i] = 0;
    if (tid < 8) ctrl[tid] = 0;
    __syncthreads();

    unsigned cnt = 0;
    for (int i = tid; i < NCLS * MDPC; i += 256) {
        float s = sc[i];
        if (s > 0.0f) { ++cnt; atomicAdd(&hist[fkey32(s) >> 20], 1u); }
    }
    for (int o = 16; o; o >>= 1) cnt += __shfl_down_sync(0xFFFFFFFFu, cnt, o);
    if ((tid & 31) == 0) atomicAdd((unsigned*)&ctrl[5], cnt);
    __syncthreads();
    const unsigned npos = (unsigned)ctrl[5];

    if (npos >= (unsigned)MAXD) {
        (void)suffix_total<16>(hist, csum, tid);
        crossing<16>(hist, csum, ctrl, MAXD, tid);
        const unsigned B1 = (unsigned)ctrl[0];
        const unsigned C1 = (unsigned)ctrl[1];
        __syncthreads();
        for (int i = tid; i < NBINF; i += 256) hist[i] = 0;
        __syncthreads();
        for (int i = tid; i < NCLS * MDPC; i += 256) {
            float s = sc[i];
            if (s > 0.0f) {
                unsigned key = fkey32(s);
                if ((key >> 20) == B1) atomicAdd(&hist[(key >> 8) & 0xFFFu], 1u);
            }
        }
        __syncthreads();
        (void)suffix_total<16>(hist, csum, tid);
        crossing<16>(hist, csum, ctrl, MAXD - C1, tid);
        const unsigned B2 = (unsigned)ctrl[0];
        if (tid == 0) ctrl[2] = 0;
        __syncthreads();
        for (int i = tid; i < NCLS * MDPC; i += 256) {
            float s = sc[i];
            if (s > 0.0f) {
                unsigned key = fkey32(s);
                unsigned l1 = key >> 20;
                bool take = l1 > B1 || (l1 == B1 && ((key >> 8) & 0xFFFu) >= B2);
                if (take) {
                    int p = atomicAdd(&ctrl[2], 1);
                    if (p < 256)
                        BUF[p] = ((unsigned long long)key << 32) | (unsigned)(~(unsigned)i);
                }
            }
        }
        __syncthreads();
    } else {
        if (tid == 0) ctrl[2] = 0;
        __syncthreads();
        for (int i = tid; i < NCLS * MDPC; i += 256) {
            float s = sc[i];
            if (s > 0.0f) {
                int p = atomicAdd(&ctrl[2], 1);
                if (p < 256)
                    BUF[p] = ((unsigned long long)fkey32(s) << 32) | (unsigned)(~(unsigned)i);
            }
        }
        __syncthreads();
    }

    int sel = ctrl[2]; if (sel > 256) sel = 256;
    if (tid >= sel) BUF[tid] = 0ull;
    __syncthreads();

    for (int kk = 2; kk <= 256; kk <<= 1) {
        for (int j = kk >> 1; j > 0; j >>= 1) {
            int ix = tid ^ j;
            if (ix > tid) {
                unsigned long long x = BUF[tid], y = BUF[ix];
                bool sw = ((tid & kk) == 0) ? (x < y) : (x > y);
                if (sw) { BUF[tid] = y; BUF[ix] = x; }
            }
            __syncthreads();
        }
    }

    if (tid == 0) vc = 0;
    __syncthreads();

    if (tid < MAXD) {
        unsigned long long e = BUF[tid];
        unsigned key  = (unsigned)(e >> 32);
        unsigned flat = ~(unsigned)(e & 0xFFFFFFFFull);
        bool valid = (key != 0u);
        float4 bx = make_float4(0.f, 0.f, 0.f, 0.f);
        float cls = 0.0f, so = 0.0f;
        if (valid) {
            float s = __uint_as_float((key & 0x80000000u) ? (key & 0x7FFFFFFFu) : ~key);
            bx  = g_cls_boxes[b * NCLS * MDPC + flat];
            cls = (float)(flat / MDPC);
            so  = s;
            atomicAdd(&vc, 1);
        }
        out[b * 400 + tid * 4 + 0] = bx.x;
        out[b * 400 + tid * 4 + 1] = bx.y;
        out[b * 400 + tid * 4 + 2] = bx.z;
        out[b * 400 + tid * 4 + 3] = bx.w;
        out[NB * MAXD * 4 + b * MAXD + tid]             = so;
        out[NB * MAXD * 4 + NB * MAXD + b * MAXD + tid] = cls;
    }
    __syncthreads();
    if (tid == 0) out[NB * MAXD * 6 + b] = (float)vc;
}

// =====================================================================
extern "C" void kernel_launch(void* const* d_in, const int* in_sizes, int n_in,
                              void* d_out, int out_size) {
    (void)in_sizes; (void)n_in; (void)out_size;
    const float* pred    = (const float*)d_in[1];
    const float* anchors = (const float*)d_in[2];
    float* out = (float*)d_out;

    k_nop<<<1, 32>>>();                      // keep ncu window on k_select
    k_zero<<<80, 256>>>();
    k_decode<<<NB * 600, 256>>>(pred);

    cudaFuncSetAttribute(k_select, cudaFuncAttributeMaxDynamicSharedMemorySize, 17920);
    k_select<<<NTASK, 256, 17920>>>(pred, anchors);

    k_final<<<NB, 256>>>(out);
}

// round 8
// speedup vs baseline: 2.5271x; 1.0019x over previous
#include <cuda_runtime.h>
#include <math.h>

#define A_N    76725
#define NCLS   80
#define NB     8
#define NTASK  (NB*NCLS)
#define KPRE   256
#define MDPC   100
#define MAXD   100
#define CCAP   3072
#define BUFN   1024
#define NBIN2  2048          // k_select fast-path bins
#define NBINF  4096          // k_final bins
#define PUSH_T 2.0f
#define CNTSTR 32
#define SEL_BASE 0xBF600000u // all fast-path keys > this (s > 0.875)
#define FIN_BASE 0xBD400000u // all positive scores > this (s > 0.046875)

__device__ unsigned long long g_cand[(size_t)NTASK * CCAP];
__device__ int    g_cnt[NTASK * CNTSTR];
__device__ float  g_cls_scores[NTASK * MDPC];
__device__ float4 g_cls_boxes[NTASK * MDPC];

__device__ __forceinline__ unsigned fkey32(float x) {
    unsigned b = __float_as_uint(x);
    return (b & 0x80000000u) ? ~b : (b | 0x80000000u);
}

template <int BPT>
__device__ __forceinline__ unsigned suffix_total(const unsigned* hist, unsigned* csum, int tid) {
    unsigned s = 0;
    const int base = tid * BPT;
#pragma unroll
    for (int r = 0; r < BPT; ++r) s += hist[base + r];
    csum[tid] = s;
    __syncthreads();
    for (int off = 1; off < 256; off <<= 1) {
        unsigned add = (tid + off < 256) ? csum[tid + off] : 0u;
        __syncthreads();
        csum[tid] += add;
        __syncthreads();
    }
    return csum[0];
}

template <int BPT>
__device__ __forceinline__ void crossing(const unsigned* hist, const unsigned* csum, int* ctrl,
                                         unsigned target, int tid) {
    unsigned run = (tid + 1 < 256) ? csum[tid + 1] : 0u;
    const int base = tid * BPT;
    for (int i = base + BPT - 1; i >= base; --i) {
        unsigned h = hist[i];
        run += h;
        if (run >= target && run - h < target) { ctrl[0] = i; ctrl[1] = (int)(run - h); }
    }
    __syncthreads();
}

// =====================================================================
__global__ void k_nop() {}

__global__ void k_zero() {
    int i = blockIdx.x * 256 + threadIdx.x;
    if (i < NTASK * CNTSTR) g_cnt[i] = 0;
}

// =====================================================================
// Kernel 1: stream predictions, push high-logit candidates
// =====================================================================
__global__ void __launch_bounds__(256) k_decode(const float* __restrict__ pred) {
    const int nT = 600;
    const int b  = blockIdx.x / nT;
    const int t  = blockIdx.x % nT;
    const int a0 = t << 7;
    const int na = min(128, A_N - a0);
    const float4* src = (const float4*)(pred + ((size_t)b * A_N + a0) * 84);
    const int tot = na * 21;

    for (int i = threadIdx.x; i < tot; i += 256) {
        float4 v = src[i];
        int la   = i / 21;
        int col0 = (i - la * 21) * 4;
        int a    = a0 + la;
        float xs[4] = { v.x, v.y, v.z, v.w };
#pragma unroll
        for (int j = 0; j < 4; ++j) {
            float x = xs[j];
            int col = col0 + j;
            if (col >= 4 && x > PUSH_T) {
                int c = col - 4;
                int task = b * NCLS + c;
                float s = 1.0f / (1.0f + expf(-x));
                int idx = atomicAdd(&g_cnt[task * CNTSTR], 1);
                if (idx < CCAP) {
                    unsigned key = __float_as_uint(s) | 0x80000000u;
                    g_cand[(size_t)task * CCAP + idx] =
                        ((unsigned long long)key << 32) | (unsigned)(~(unsigned)a);
                }
            }
        }
    }
}

// =====================================================================
// Kernel 2: per (b,c) exact top-256 + greedy NMS + per-class top-100
// =====================================================================
__global__ void __launch_bounds__(256, 6) k_select(const float* __restrict__ pred,
                                                   const float* __restrict__ anchors) {
    extern __shared__ unsigned char sm[];
    unsigned*           hist = (unsigned*)sm;                      // 8KB
    unsigned*           csum = (unsigned*)(sm + 8192);             // 1028B
    int*                ctrl = (int*)(sm + 9232);
    unsigned long long* BUF  = (unsigned long long*)(sm + 9728);   // 8KB

    const int tid  = threadIdx.x;
    const int task = blockIdx.x;
    const int b    = task / NCLS;
    const int c    = task % NCLS;

    const int n = g_cnt[task * CNTSTR];
    bool fallback = !(n >= KPRE && n <= CCAP);
    const unsigned long long* cand = g_cand + (size_t)task * CCAP;

    for (int i = tid; i < NBIN2; i += 256) hist[i] = 0;
    if (tid < 8) ctrl[tid] = 0;
    __syncthreads();

    if (!fallback) {
        // single-level histogram on spread mantissa bins (all keys share exp 126)
        for (int i = tid; i < n; i += 256) {
            unsigned key = (unsigned)(cand[i] >> 32);
            atomicAdd(&hist[(key - SEL_BASE) >> 10], 1u);
        }
        __syncthreads();
        (void)suffix_total<8>(hist, csum, tid);
        crossing<8>(hist, csum, ctrl, KPRE, tid);
        const unsigned B1 = (unsigned)ctrl[0];
        const unsigned C1 = (unsigned)ctrl[1];
        const unsigned need = C1 + hist[B1];       // above + whole tie bin
        __syncthreads();

        if (need <= (unsigned)BUFN) {
            const unsigned minKey = SEL_BASE + (B1 << 10);
            if (tid == 0) ctrl[2] = 0;
            __syncthreads();
            for (int i = tid; i < n; i += 256) {
                unsigned long long e = cand[i];
                if ((unsigned)(e >> 32) >= minKey) {
                    int p = atomicAdd(&ctrl[2], 1);
                    BUF[p] = e;
                }
            }
            __syncthreads();
        } else {
            fallback = true;
        }
    }

    if (fallback) {
        // exact generic path: strided rescan of this class column
        for (int i = tid; i < NBIN2; i += 256) hist[i] = 0;
        if (tid < 8) ctrl[tid] = 0;
        __syncthreads();
        unsigned cnt = 0;
        for (int a = tid; a < A_N; a += 256) {
            float x = pred[((size_t)b * A_N + a) * 84 + 4 + c];
            float s = 1.0f / (1.0f + expf(-x));
            if (s > 0.05f) { ++cnt; atomicAdd(&hist[fkey32(s) >> 21], 1u); }
        }
        for (int o = 16; o; o >>= 1) cnt += __shfl_down_sync(0xFFFFFFFFu, cnt, o);
        if ((tid & 31) == 0) atomicAdd((unsigned*)&ctrl[5], cnt);
        __syncthreads();
        const unsigned total = (unsigned)ctrl[5];
        if (total == 0u) {
            for (int p = tid; p < MDPC; p += 256) {
                g_cls_scores[task * MDPC + p] = -1.0f;
                g_cls_boxes [task * MDPC + p] = make_float4(0.f, 0.f, 0.f, 0.f);
            }
            return;
        }
        const unsigned target = total < (unsigned)KPRE ? total : (unsigned)KPRE;
        (void)suffix_total<8>(hist, csum, tid);
        crossing<8>(hist, csum, ctrl, target, tid);
        const unsigned B1 = (unsigned)ctrl[0];
        const unsigned C1 = (unsigned)ctrl[1];
        __syncthreads();
        for (int i = tid; i < NBIN2; i += 256) hist[i] = 0;
        __syncthreads();
        for (int a = tid; a < A_N; a += 256) {
            float x = pred[((size_t)b * A_N + a) * 84 + 4 + c];
            float s = 1.0f / (1.0f + expf(-x));
            if (s > 0.05f) {
                unsigned key = fkey32(s);
                if ((key >> 21) == B1) atomicAdd(&hist[(key >> 10) & 0x7FFu], 1u);
            }
        }
        __syncthreads();
        (void)suffix_total<8>(hist, csum, tid);
        crossing<8>(hist, csum, ctrl, target - C1, tid);
        const unsigned B2 = (unsigned)ctrl[0];
        if (tid == 0) ctrl[2] = 0;
        __syncthreads();
        for (int a = tid; a < A_N; a += 256) {
            float x = pred[((size_t)b * A_N + a) * 84 + 4 + c];
            float s = 1.0f / (1.0f + expf(-x));
            if (s > 0.05f) {
                unsigned key = fkey32(s);
                unsigned l1 = key >> 21;
                bool take = l1 > B1 || (l1 == B1 && ((key >> 10) & 0x7FFu) >= B2);
                if (take) {
                    int p = atomicAdd(&ctrl[2], 1);
                    if (p < BUFN)
                        BUF[p] = ((unsigned long long)key << 32) | (unsigned)(~(unsigned)a);
                }
            }
        }
        __syncthreads();
    }

    int sel = ctrl[2]; if (sel > BUFN) sel = BUFN;
    const int W = (sel <= 512) ? 512 : 1024;
    for (int i = sel + tid; i < W; i += 256) BUF[i] = 0ull;
    __syncthreads();

    for (int kk = 2; kk <= W; kk <<= 1) {
        for (int j = kk >> 1; j > 0; j >>= 1) {
            for (int i = tid; i < W; i += 256) {
                int ix = i ^ j;
                if (ix > i) {
                    unsigned long long x = BUF[i], y = BUF[ix];
                    bool sw = ((i & kk) == 0) ? (x < y) : (x > y);
                    if (sw) { BUF[i] = y; BUF[ix] = x; }
                }
            }
            __syncthreads();
        }
    }

    // ---- NMS on top-256 ----
    float*    X1    = (float*)sm;
    float*    Y1    = (float*)(sm + 1024);
    float*    X2    = (float*)(sm + 2048);
    float*    Y2    = (float*)(sm + 3072);
    float*    AR    = (float*)(sm + 4096);
    float*    SC    = (float*)(sm + 5120);
    unsigned* MASKS = (unsigned*)(sm + 6144);
    unsigned* KEEPW = (unsigned*)(sm + 14336);
    unsigned* WPFX  = (unsigned*)(sm + 14400);

    {
        unsigned long long e = BUF[tid];
        unsigned key  = (unsigned)(e >> 32);
        unsigned aidx = ~(unsigned)(e & 0xFFFFFFFFull);
        float  s  = -1.0f;
        float4 bx = make_float4(0.f, 0.f, 0.f, 0.f);
        if (key) {
            const float4 bp = *(const float4*)(pred + ((size_t)b * A_N + aidx) * 84);
            const float4 an = ((const float4*)anchors)[aidx];
            float cx = bp.x * 0.1f * an.z + an.x;
            float cy = bp.y * 0.1f * an.w + an.y;
            float w  = expf(bp.z * 0.2f) * an.z;
            float h  = expf(bp.w * 0.2f) * an.w;
            bx = make_float4(cx - w * 0.5f, cy - h * 0.5f, cx + w * 0.5f, cy + h * 0.5f);
            s  = __uint_as_float(key & 0x7FFFFFFFu);
        }
        X1[tid] = bx.x; Y1[tid] = bx.y; X2[tid] = bx.z; Y2[tid] = bx.w;
        AR[tid] = (bx.z - bx.x) * (bx.w - bx.y);
        SC[tid] = s;
        unsigned bal = __ballot_sync(0xFFFFFFFFu, key != 0u);
        if ((tid & 31) == 0) KEEPW[tid >> 5] = bal;
    }
    __syncthreads();

    {
        float ax1 = X1[tid], ay1 = Y1[tid], ax2 = X2[tid], ay2 = Y2[tid], aa = AR[tid];
        for (int w = 0; w < 8; ++w) {
            unsigned m = 0;
            for (int l = 0; l < 32; ++l) {
                int j = w * 32 + l;
                if (j > tid) {
                    float iw = fmaxf(fminf(ax2, X2[j]) - fmaxf(ax1, X1[j]), 0.f);
                    float ih = fmaxf(fminf(ay2, Y2[j]) - fmaxf(ay1, Y1[j]), 0.f);
                    float inter = iw * ih;
                    float iou = inter / fmaxf(aa + AR[j] - inter, 1e-8f);
                    if (iou > 0.5f) m |= (1u << l);
                }
            }
            MASKS[tid * 8 + w] = m;
        }
    }
    __syncthreads();

    if (tid < 32) {
        unsigned kw = (tid < 8) ? KEEPW[tid] : 0u;
        for (int i = 0; i < 256; ++i) {
            unsigned word = __shfl_sync(0xFFFFFFFFu, kw, i >> 5);
            if ((word >> (i & 31)) & 1u) {
                if (tid < 8) kw &= ~MASKS[i * 8 + tid];
            }
        }
        if (tid < 8) KEEPW[tid] = kw;
    }
    __syncthreads();

    if (tid == 0) {
        unsigned run = 0;
        for (int w = 0; w < 8; ++w) { WPFX[w] = run; run += __popc(KEEPW[w]); }
        WPFX[8] = run;
    }
    __syncthreads();

    {
        unsigned w = tid >> 5, bpos = tid & 31;
        unsigned kwv = KEEPW[w];
        bool kept = (kwv >> bpos) & 1u;
        unsigned p = WPFX[w] + __popc(kwv & ((1u << bpos) - 1u));
        if (kept && p < MDPC) {
            g_cls_scores[task * MDPC + p] = SC[tid];
            g_cls_boxes [task * MDPC + p] = make_float4(X1[tid], Y1[tid], X2[tid], Y2[tid]);
        }
        int kc = (int)WPFX[8];
        for (int q = kc + tid; q < MDPC; q += 256) {
            g_cls_scores[task * MDPC + q] = -1.0f;
            g_cls_boxes [task * MDPC + q] = make_float4(0.f, 0.f, 0.f, 0.f);
        }
    }
}

// =====================================================================
// Kernel 3: per image top-100 of 8000 (spread bins: no atomic storm)
// =====================================================================
__global__ void __launch_bounds__(256) k_final(float* __restrict__ out) {
    __shared__ unsigned hist[NBINF];
    __shared__ unsigned long long BUF[256];
    __shared__ unsigned csum[257];
    __shared__ int ctrl[8];
    __shared__ int vc;

    const int tid = threadIdx.x;
    const int b   = blockIdx.x;
    const float* sc = g_cls_scores + b * NCLS * MDPC;

    for (int i = tid; i < NBINF; i += 256) hist[i] = 0;
    if (tid < 8) ctrl[tid] = 0;
    __syncthreads();

    unsigned cnt = 0;
    for (int i = tid; i < NCLS * MDPC; i += 256) {
        float s = sc[i];
        if (s > 0.0f) { ++cnt; atomicAdd(&hist[(fkey32(s) - FIN_BASE) >> 14], 1u); }
    }
    for (int o = 16; o; o >>= 1) cnt += __shfl_down_sync(0xFFFFFFFFu, cnt, o);
    if ((tid & 31) == 0) atomicAdd((unsigned*)&ctrl[5], cnt);
    __syncthreads();
    const unsigned npos = (unsigned)ctrl[5];

    if (npos >= (unsigned)MAXD) {
        (void)suffix_total<16>(hist, csum, tid);
        crossing<16>(hist, csum, ctrl, MAXD, tid);
        const unsigned B1 = (unsigned)ctrl[0];
        const unsigned C1 = (unsigned)ctrl[1];
        __syncthreads();
        for (int i = tid; i < NBINF; i += 256) hist[i] = 0;
        __syncthreads();
        for (int i = tid; i < NCLS * MDPC; i += 256) {
            float s = sc[i];
            if (s > 0.0f) {
                unsigned key = fkey32(s);
                if (((key - FIN_BASE) >> 14) == B1) atomicAdd(&hist[(key >> 2) & 0xFFFu], 1u);
            }
        }
        __syncthreads();
        (void)suffix_total<16>(hist, csum, tid);
        crossing<16>(hist, csum, ctrl, MAXD - C1, tid);
        const unsigned B2 = (unsigned)ctrl[0];
        if (tid == 0) ctrl[2] = 0;
        __syncthreads();
        for (int i = tid; i < NCLS * MDPC; i += 256) {
            float s = sc[i];
            if (s > 0.0f) {
                unsigned key = fkey32(s);
                unsigned l1 = (key - FIN_BASE) >> 14;
                bool take = l1 > B1 || (l1 == B1 && ((key >> 2) & 0xFFFu) >= B2);
                if (take) {
                    int p = atomicAdd(&ctrl[2], 1);
                    if (p < 256)
                        BUF[p] = ((unsigned long long)key << 32) | (unsigned)(~(unsigned)i);
                }
            }
        }
        __syncthreads();
    } else {
        if (tid == 0) ctrl[2] = 0;
        __syncthreads();
        for (int i = tid; i < NCLS * MDPC; i += 256) {
            float s = sc[i];
            if (s > 0.0f) {
                int p = atomicAdd(&ctrl[2], 1);
                if (p < 256)
                    BUF[p] = ((unsigned long long)fkey32(s) << 32) | (unsigned)(~(unsigned)i);
            }
        }
        __syncthreads();
    }

    int sel = ctrl[2]; if (sel > 256) sel = 256;
    if (tid >= sel) BUF[tid] = 0ull;
    __syncthreads();

    for (int kk = 2; kk <= 256; kk <<= 1) {
        for (int j = kk >> 1; j > 0; j >>= 1) {
            int ix = tid ^ j;
            if (ix > tid) {
                unsigned long long x = BUF[tid], y = BUF[ix];
                bool sw = ((tid & kk) == 0) ? (x < y) : (x > y);
                if (sw) { BUF[tid] = y; BUF[ix] = x; }
            }
            __syncthreads();
        }
    }

    if (tid == 0) vc = 0;
    __syncthreads();

    if (tid < MAXD) {
        unsigned long long e = BUF[tid];
        unsigned key  = (unsigned)(e >> 32);
        unsigned flat = ~(unsigned)(e & 0xFFFFFFFFull);
        bool valid = (key != 0u);
        float4 bx = make_float4(0.f, 0.f, 0.f, 0.f);
        float cls = 0.0f, so = 0.0f;
        if (valid) {
            float s = __uint_as_float((key & 0x80000000u) ? (key & 0x7FFFFFFFu) : ~key);
            bx  = g_cls_boxes[b * NCLS * MDPC + flat];
            cls = (float)(flat / MDPC);
            so  = s;
            atomicAdd(&vc, 1);
        }
        out[b * 400 + tid * 4 + 0] = bx.x;
        out[b * 400 + tid * 4 + 1] = bx.y;
        out[b * 400 + tid * 4 + 2] = bx.z;
        out[b * 400 + tid * 4 + 3] = bx.w;
        out[NB * MAXD * 4 + b * MAXD + tid]             = so;
        out[NB * MAXD * 4 + NB * MAXD + b * MAXD + tid] = cls;
    }
    __syncthreads();
    if (tid == 0) out[NB * MAXD * 6 + b] = (float)vc;
}

// =====================================================================
extern "C" void kernel_launch(void* const* d_in, const int* in_sizes, int n_in,
                              void* d_out, int out_size) {
    (void)in_sizes; (void)n_in; (void)out_size;
    const float* pred    = (const float*)d_in[1];
    const float* anchors = (const float*)d_in[2];
    float* out = (float*)d_out;

    k_nop<<<1, 32>>>();                      // two nops: ncu window lands on k_decode
    k_nop<<<1, 32>>>();
    k_zero<<<80, 256>>>();
    k_decode<<<NB * 600, 256>>>(pred);

    cudaFuncSetAttribute(k_select, cudaFuncAttributeMaxDynamicSharedMemorySize, 17920);
    k_select<<<NTASK, 256, 17920>>>(pred, anchors);

    k_final<<<NB, 256>>>(out);
}

// round 9
// speedup vs baseline: 2.9757x; 1.1775x over previous
#include <cuda_runtime.h>
#include <math.h>

#define A_N    76725
#define NCLS   80
#define NB     8
#define NTASK  (NB*NCLS)
#define KPRE   256
#define MDPC   100
#define MAXD   100
#define CCAP   3072
#define BUFN   1024
#define NBIN2  2048
#define NBINF  4096
#define PUSH_T 2.0f
#define CNTSTR 32
#define SEL_BASE 0xBF600000u
#define FIN_BASE 0xBD400000u

__device__ unsigned long long g_cand[(size_t)NTASK * CCAP];
__device__ int    g_cnt[NTASK * CNTSTR];
__device__ float  g_cls_scores[NTASK * MDPC];
__device__ float4 g_cls_boxes[NTASK * MDPC];

__device__ __forceinline__ unsigned fkey32(float x) {
    unsigned b = __float_as_uint(x);
    return (b & 0x80000000u) ? ~b : (b | 0x80000000u);
}

template <int BPT>
__device__ __forceinline__ unsigned suffix_total(const unsigned* hist, unsigned* csum, int tid) {
    unsigned s = 0;
    const int base = tid * BPT;
#pragma unroll
    for (int r = 0; r < BPT; ++r) s += hist[base + r];
    csum[tid] = s;
    __syncthreads();
    for (int off = 1; off < 256; off <<= 1) {
        unsigned add = (tid + off < 256) ? csum[tid + off] : 0u;
        __syncthreads();
        csum[tid] += add;
        __syncthreads();
    }
    return csum[0];
}

template <int BPT>
__device__ __forceinline__ void crossing(const unsigned* hist, const unsigned* csum, int* ctrl,
                                         unsigned target, int tid) {
    unsigned run = (tid + 1 < 256) ? csum[tid + 1] : 0u;
    const int base = tid * BPT;
    for (int i = base + BPT - 1; i >= base; --i) {
        unsigned h = hist[i];
        run += h;
        if (run >= target && run - h < target) { ctrl[0] = i; ctrl[1] = (int)(run - h); }
    }
    __syncthreads();
}

// =====================================================================
__global__ void k_nop() {}

__global__ void k_zero() {
    int i = blockIdx.x * 256 + threadIdx.x;
    if (i < NTASK * CNTSTR) g_cnt[i] = 0;
}

// =====================================================================
// Kernel 1: stream predictions with deep MLP, push high-logit candidates
// =====================================================================
__device__ __forceinline__ void dec_process(float4 v, int i, int b, int a0) {
    int la   = i / 21;
    int col0 = (i - la * 21) * 4;
    int a    = a0 + la;
    float xs[4] = { v.x, v.y, v.z, v.w };
#pragma unroll
    for (int j = 0; j < 4; ++j) {
        float x = xs[j];
        int col = col0 + j;
        if (col >= 4 && x > PUSH_T) {
            int c = col - 4;
            int task = b * NCLS + c;
            float s = 1.0f / (1.0f + expf(-x));
            int idx = atomicAdd(&g_cnt[task * CNTSTR], 1);
            if (idx < CCAP) {
                unsigned key = __float_as_uint(s) | 0x80000000u;
                g_cand[(size_t)task * CCAP + idx] =
                    ((unsigned long long)key << 32) | (unsigned)(~(unsigned)a);
            }
        }
    }
}

__global__ void __launch_bounds__(256) k_decode(const float* __restrict__ pred) {
    const int nT = 600;
    const int b  = blockIdx.x / nT;
    const int t  = blockIdx.x % nT;
    const int a0 = t << 7;
    const int na = min(128, A_N - a0);
    const float4* src = (const float4*)(pred + ((size_t)b * A_N + a0) * 84);
    const int tid = threadIdx.x;

    if (na == 128) {
        // 128 anchors * 21 float4 = 2688 = 10*256 + 128
        float4 v[10];
#pragma unroll
        for (int k = 0; k < 10; ++k) v[k] = src[tid + k * 256];   // 10 independent LDG.128
        float4 vt;
        const bool tl = tid < 128;
        if (tl) vt = src[2560 + tid];
#pragma unroll
        for (int k = 0; k < 10; ++k) dec_process(v[k], tid + k * 256, b, a0);
        if (tl) dec_process(vt, 2560 + tid, b, a0);
    } else {
        const int tot = na * 21;
        for (int i = tid; i < tot; i += 256) dec_process(src[i], i, b, a0);
    }
}

// =====================================================================
// Kernel 2: per (b,c) exact top-256 + greedy NMS + per-class top-100
// =====================================================================
__global__ void __launch_bounds__(256, 6) k_select(const float* __restrict__ pred,
                                                   const float* __restrict__ anchors) {
    extern __shared__ unsigned char sm[];
    unsigned*           hist = (unsigned*)sm;                      // 8KB
    unsigned*           csum = (unsigned*)(sm + 8192);
    int*                ctrl = (int*)(sm + 9232);
    unsigned long long* BUF  = (unsigned long long*)(sm + 9728);   // 8KB

    const int tid  = threadIdx.x;
    const int task = blockIdx.x;
    const int b    = task / NCLS;
    const int c    = task % NCLS;

    const int n = g_cnt[task * CNTSTR];
    bool fallback = !(n >= KPRE && n <= CCAP);
    const unsigned long long* cand = g_cand + (size_t)task * CCAP;

    for (int i = tid; i < NBIN2; i += 256) hist[i] = 0;
    if (tid < 8) ctrl[tid] = 0;
    __syncthreads();

    if (!fallback) {
        for (int i = tid; i < n; i += 256) {
            unsigned key = (unsigned)(cand[i] >> 32);
            atomicAdd(&hist[(key - SEL_BASE) >> 10], 1u);
        }
        __syncthreads();
        (void)suffix_total<8>(hist, csum, tid);
        crossing<8>(hist, csum, ctrl, KPRE, tid);
        const unsigned B1 = (unsigned)ctrl[0];
        const unsigned C1 = (unsigned)ctrl[1];
        const unsigned need = C1 + hist[B1];
        __syncthreads();

        if (need <= (unsigned)BUFN) {
            const unsigned minKey = SEL_BASE + (B1 << 10);
            if (tid == 0) ctrl[2] = 0;
            __syncthreads();
            for (int i = tid; i < n; i += 256) {
                unsigned long long e = cand[i];
                if ((unsigned)(e >> 32) >= minKey) {
                    int p = atomicAdd(&ctrl[2], 1);
                    BUF[p] = e;
                }
            }
            __syncthreads();
        } else {
            fallback = true;
        }
    }

    if (fallback) {
        for (int i = tid; i < NBIN2; i += 256) hist[i] = 0;
        if (tid < 8) ctrl[tid] = 0;
        __syncthreads();
        unsigned cnt = 0;
        for (int a = tid; a < A_N; a += 256) {
            float x = pred[((size_t)b * A_N + a) * 84 + 4 + c];
            float s = 1.0f / (1.0f + expf(-x));
            if (s > 0.05f) { ++cnt; atomicAdd(&hist[fkey32(s) >> 21], 1u); }
        }
        for (int o = 16; o; o >>= 1) cnt += __shfl_down_sync(0xFFFFFFFFu, cnt, o);
        if ((tid & 31) == 0) atomicAdd((unsigned*)&ctrl[5], cnt);
        __syncthreads();
        const unsigned total = (unsigned)ctrl[5];
        if (total == 0u) {
            for (int p = tid; p < MDPC; p += 256) {
                g_cls_scores[task * MDPC + p] = -1.0f;
                g_cls_boxes [task * MDPC + p] = make_float4(0.f, 0.f, 0.f, 0.f);
            }
            return;
        }
        const unsigned target = total < (unsigned)KPRE ? total : (unsigned)KPRE;
        (void)suffix_total<8>(hist, csum, tid);
        crossing<8>(hist, csum, ctrl, target, tid);
        const unsigned B1 = (unsigned)ctrl[0];
        const unsigned C1 = (unsigned)ctrl[1];
        __syncthreads();
        for (int i = tid; i < NBIN2; i += 256) hist[i] = 0;
        __syncthreads();
        for (int a = tid; a < A_N; a += 256) {
            float x = pred[((size_t)b * A_N + a) * 84 + 4 + c];
            float s = 1.0f / (1.0f + expf(-x));
            if (s > 0.05f) {
                unsigned key = fkey32(s);
                if ((key >> 21) == B1) atomicAdd(&hist[(key >> 10) & 0x7FFu], 1u);
            }
        }
        __syncthreads();
        (void)suffix_total<8>(hist, csum, tid);
        crossing<8>(hist, csum, ctrl, target - C1, tid);
        const unsigned B2 = (unsigned)ctrl[0];
        if (tid == 0) ctrl[2] = 0;
        __syncthreads();
        for (int a = tid; a < A_N; a += 256) {
            float x = pred[((size_t)b * A_N + a) * 84 + 4 + c];
            float s = 1.0f / (1.0f + expf(-x));
            if (s > 0.05f) {
                unsigned key = fkey32(s);
                unsigned l1 = key >> 21;
                bool take = l1 > B1 || (l1 == B1 && ((key >> 10) & 0x7FFu) >= B2);
                if (take) {
                    int p = atomicAdd(&ctrl[2], 1);
                    if (p < BUFN)
                        BUF[p] = ((unsigned long long)key << 32) | (unsigned)(~(unsigned)a);
                }
            }
        }
        __syncthreads();
    }

    int sel = ctrl[2]; if (sel > BUFN) sel = BUFN;
    const int W = (sel <= 512) ? 512 : 1024;
    for (int i = sel + tid; i < W; i += 256) BUF[i] = 0ull;
    __syncthreads();

    for (int kk = 2; kk <= W; kk <<= 1) {
        for (int j = kk >> 1; j > 0; j >>= 1) {
            for (int i = tid; i < W; i += 256) {
                int ix = i ^ j;
                if (ix > i) {
                    unsigned long long x = BUF[i], y = BUF[ix];
                    bool sw = ((i & kk) == 0) ? (x < y) : (x > y);
                    if (sw) { BUF[i] = y; BUF[ix] = x; }
                }
            }
            __syncthreads();
        }
    }

    // ---- NMS on top-256 ----
    float*    X1    = (float*)sm;
    float*    Y1    = (float*)(sm + 1024);
    float*    X2    = (float*)(sm + 2048);
    float*    Y2    = (float*)(sm + 3072);
    float*    AR    = (float*)(sm + 4096);
    float*    SC    = (float*)(sm + 5120);
    unsigned* MASKS = (unsigned*)(sm + 6144);
    unsigned* KEEPW = (unsigned*)(sm + 14336);
    unsigned* WPFX  = (unsigned*)(sm + 14400);

    {
        unsigned long long e = BUF[tid];
        unsigned key  = (unsigned)(e >> 32);
        unsigned aidx = ~(unsigned)(e & 0xFFFFFFFFull);
        float  s  = -1.0f;
        float4 bx = make_float4(0.f, 0.f, 0.f, 0.f);
        if (key) {
            const float4 bp = *(const float4*)(pred + ((size_t)b * A_N + aidx) * 84);
            const float4 an = ((const float4*)anchors)[aidx];
            float cx = bp.x * 0.1f * an.z + an.x;
            float cy = bp.y * 0.1f * an.w + an.y;
            float w  = expf(bp.z * 0.2f) * an.z;
            float h  = expf(bp.w * 0.2f) * an.w;
            bx = make_float4(cx - w * 0.5f, cy - h * 0.5f, cx + w * 0.5f, cy + h * 0.5f);
            s  = __uint_as_float(key & 0x7FFFFFFFu);
        }
        X1[tid] = bx.x; Y1[tid] = bx.y; X2[tid] = bx.z; Y2[tid] = bx.w;
        AR[tid] = (bx.z - bx.x) * (bx.w - bx.y);
        SC[tid] = s;
        unsigned bal = __ballot_sync(0xFFFFFFFFu, key != 0u);
        if ((tid & 31) == 0) KEEPW[tid >> 5] = bal;
    }
    __syncthreads();

    {   // triangular suppression mask: j in (tid, 256), divide-free IoU test
        float ax1 = X1[tid], ay1 = Y1[tid], ax2 = X2[tid], ay2 = Y2[tid], aa = AR[tid];
        const int w0 = tid >> 5;
        for (int w = 0; w < w0; ++w) MASKS[tid * 8 + w] = 0u;
        for (int w = w0; w < 8; ++w) {
            unsigned m = 0;
            int l0 = (w == w0) ? (tid & 31) + 1 : 0;
            for (int l = l0; l < 32; ++l) {
                int j = w * 32 + l;
                float iw = fmaxf(fminf(ax2, X2[j]) - fmaxf(ax1, X1[j]), 0.f);
                float ih = fmaxf(fminf(ay2, Y2[j]) - fmaxf(ay1, Y1[j]), 0.f);
                float inter = iw * ih;
                float thr = 0.5f * fmaxf(aa + AR[j] - inter, 1e-8f);
                if (inter > thr) m |= (1u << l);
            }
            MASKS[tid * 8 + w] = m;
        }
    }
    __syncthreads();

    if (tid < 32) {
        unsigned kw = (tid < 8) ? KEEPW[tid] : 0u;
        for (int i = 0; i < 256; ++i) {
            unsigned word = __shfl_sync(0xFFFFFFFFu, kw, i >> 5);
            if ((word >> (i & 31)) & 1u) {
                if (tid < 8) kw &= ~MASKS[i * 8 + tid];
            }
        }
        if (tid < 8) KEEPW[tid] = kw;
    }
    __syncthreads();

    if (tid == 0) {
        unsigned run = 0;
        for (int w = 0; w < 8; ++w) { WPFX[w] = run; run += __popc(KEEPW[w]); }
        WPFX[8] = run;
    }
    __syncthreads();

    {
        unsigned w = tid >> 5, bpos = tid & 31;
        unsigned kwv = KEEPW[w];
        bool kept = (kwv >> bpos) & 1u;
        unsigned p = WPFX[w] + __popc(kwv & ((1u << bpos) - 1u));
        if (kept && p < MDPC) {
            g_cls_scores[task * MDPC + p] = SC[tid];
            g_cls_boxes [task * MDPC + p] = make_float4(X1[tid], Y1[tid], X2[tid], Y2[tid]);
        }
        int kc = (int)WPFX[8];
        for (int q = kc + tid; q < MDPC; q += 256) {
            g_cls_scores[task * MDPC + q] = -1.0f;
            g_cls_boxes [task * MDPC + q] = make_float4(0.f, 0.f, 0.f, 0.f);
        }
    }
}

// =====================================================================
// Kernel 3: per image top-100 of 8000
// =====================================================================
__global__ void __launch_bounds__(256) k_final(float* __restrict__ out) {
    __shared__ unsigned hist[NBINF];
    __shared__ unsigned long long BUF[256];
    __shared__ unsigned csum[257];
    __shared__ int ctrl[8];
    __shared__ int vc;

    const int tid = threadIdx.x;
    const int b   = blockIdx.x;
    const float* sc = g_cls_scores + b * NCLS * MDPC;

    for (int i = tid; i < NBINF; i += 256) hist[i] = 0;
    if (tid < 8) ctrl[tid] = 0;
    __syncthreads();

    unsigned cnt = 0;
    for (int i = tid; i < NCLS * MDPC; i += 256) {
        float s = sc[i];
        if (s > 0.0f) { ++cnt; atomicAdd(&hist[(fkey32(s) - FIN_BASE) >> 14], 1u); }
    }
    for (int o = 16; o; o >>= 1) cnt += __shfl_down_sync(0xFFFFFFFFu, cnt, o);
    if ((tid & 31) == 0) atomicAdd((unsigned*)&ctrl[5], cnt);
    __syncthreads();
    const unsigned npos = (unsigned)ctrl[5];

    if (npos >= (unsigned)MAXD) {
        (void)suffix_total<16>(hist, csum, tid);
        crossing<16>(hist, csum, ctrl, MAXD, tid);
        const unsigned B1 = (unsigned)ctrl[0];
        const unsigned C1 = (unsigned)ctrl[1];
        __syncthreads();
        for (int i = tid; i < NBINF; i += 256) hist[i] = 0;
        __syncthreads();
        for (int i = tid; i < NCLS * MDPC; i += 256) {
            float s = sc[i];
            if (s > 0.0f) {
                unsigned key = fkey32(s);
                if (((key - FIN_BASE) >> 14) == B1) atomicAdd(&hist[(key >> 2) & 0xFFFu], 1u);
            }
        }
        __syncthreads();
        (void)suffix_total<16>(hist, csum, tid);
        crossing<16>(hist, csum, ctrl, MAXD - C1, tid);
        const unsigned B2 = (unsigned)ctrl[0];
        if (tid == 0) ctrl[2] = 0;
        __syncthreads();
        for (int i = tid; i < NCLS * MDPC; i += 256) {
            float s = sc[i];
            if (s > 0.0f) {
                unsigned key = fkey32(s);
                unsigned l1 = (key - FIN_BASE) >> 14;
                bool take = l1 > B1 || (l1 == B1 && ((key >> 2) & 0xFFFu) >= B2);
                if (take) {
                    int p = atomicAdd(&ctrl[2], 1);
                    if (p < 256)
                        BUF[p] = ((unsigned long long)key << 32) | (unsigned)(~(unsigned)i);
                }
            }
        }
        __syncthreads();
    } else {
        if (tid == 0) ctrl[2] = 0;
        __syncthreads();
        for (int i = tid; i < NCLS * MDPC; i += 256) {
            float s = sc[i];
            if (s > 0.0f) {
                int p = atomicAdd(&ctrl[2], 1);
                if (p < 256)
                    BUF[p] = ((unsigned long long)fkey32(s) << 32) | (unsigned)(~(unsigned)i);
            }
        }
        __syncthreads();
    }

    int sel = ctrl[2]; if (sel > 256) sel = 256;
    if (tid >= sel) BUF[tid] = 0ull;
    __syncthreads();

    for (int kk = 2; kk <= 256; kk <<= 1) {
        for (int j = kk >> 1; j > 0; j >>= 1) {
            int ix = tid ^ j;
            if (ix > tid) {
                unsigned long long x = BUF[tid], y = BUF[ix];
                bool sw = ((tid & kk) == 0) ? (x < y) : (x > y);
                if (sw) { BUF[tid] = y; BUF[ix] = x; }
            }
            __syncthreads();
        }
    }

    if (tid == 0) vc = 0;
    __syncthreads();

    if (tid < MAXD) {
        unsigned long long e = BUF[tid];
        unsigned key  = (unsigned)(e >> 32);
        unsigned flat = ~(unsigned)(e & 0xFFFFFFFFull);
        bool valid = (key != 0u);
        float4 bx = make_float4(0.f, 0.f, 0.f, 0.f);
        float cls = 0.0f, so = 0.0f;
        if (valid) {
            float s = __uint_as_float((key & 0x80000000u) ? (key & 0x7FFFFFFFu) : ~key);
            bx  = g_cls_boxes[b * NCLS * MDPC + flat];
            cls = (float)(flat / MDPC);
            so  = s;
            atomicAdd(&vc, 1);
        }
        out[b * 400 + tid * 4 + 0] = bx.x;
        out[b * 400 + tid * 4 + 1] = bx.y;
        out[b * 400 + tid * 4 + 2] = bx.z;
        out[b * 400 + tid * 4 + 3] = bx.w;
        out[NB * MAXD * 4 + b * MAXD + tid]             = so;
        out[NB * MAXD * 4 + NB * MAXD + b * MAXD + tid] = cls;
    }
    __syncthreads();
    if (tid == 0) out[NB * MAXD * 6 + b] = (float)vc;
}

// =====================================================================
extern "C" void kernel_launch(void* const* d_in, const int* in_sizes, int n_in,
                              void* d_out, int out_size) {
    (void)in_sizes; (void)n_in; (void)out_size;
    const float* pred    = (const float*)d_in[1];
    const float* anchors = (const float*)d_in[2];
    float* out = (float*)d_out;

    k_nop<<<1, 32>>>();                      // ncu window lands on k_select
    k_zero<<<80, 256>>>();
    k_decode<<<NB * 600, 256>>>(pred);

    cudaFuncSetAttribute(k_select, cudaFuncAttributeMaxDynamicSharedMemorySize, 17920);
    k_select<<<NTASK, 256, 17920>>>(pred, anchors);

    k_final<<<NB, 256>>>(out);
}

// round 10
// speedup vs baseline: 4.3476x; 1.4610x over previous
#include <cuda_runtime.h>
#include <math.h>

#define A_N    76725
#define NCLS   80
#define NB     8
#define NTASK  (NB*NCLS)
#define KPRE   256
#define MDPC   100
#define MAXD   100
#define CCAP   3072
#define BUFN   1024
#define NBIN2  2048
#define NBINF  4096
#define PUSH_T 2.5f
#define CNTSTR 32
#define SEL_BASE 0xBF600000u
#define FIN_BASE 0xBD400000u

__device__ unsigned long long g_cand[(size_t)NTASK * CCAP];
__device__ int    g_cnt[NTASK * CNTSTR];
__device__ float  g_cls_scores[NTASK * MDPC];
__device__ float4 g_cls_boxes[NTASK * MDPC];

__device__ __forceinline__ unsigned fkey32(float x) {
    unsigned b = __float_as_uint(x);
    return (b & 0x80000000u) ? ~b : (b | 0x80000000u);
}

template <int BPT>
__device__ __forceinline__ unsigned suffix_total(const unsigned* hist, unsigned* csum, int tid) {
    unsigned s = 0;
    const int base = tid * BPT;
#pragma unroll
    for (int r = 0; r < BPT; ++r) s += hist[base + r];
    csum[tid] = s;
    __syncthreads();
    for (int off = 1; off < 256; off <<= 1) {
        unsigned add = (tid + off < 256) ? csum[tid + off] : 0u;
        __syncthreads();
        csum[tid] += add;
        __syncthreads();
    }
    return csum[0];
}

template <int BPT>
__device__ __forceinline__ void crossing(const unsigned* hist, const unsigned* csum, int* ctrl,
                                         unsigned target, int tid) {
    unsigned run = (tid + 1 < 256) ? csum[tid + 1] : 0u;
    const int base = tid * BPT;
    for (int i = base + BPT - 1; i >= base; --i) {
        unsigned h = hist[i];
        run += h;
        if (run >= target && run - h < target) { ctrl[0] = i; ctrl[1] = (int)(run - h); }
    }
    __syncthreads();
}

// =====================================================================
__global__ void k_nop() {}

__global__ void k_zero() {
    int i = blockIdx.x * 256 + threadIdx.x;
    if (i < NTASK * CNTSTR) g_cnt[i] = 0;
}

// =====================================================================
// Kernel 1: stream predictions (MLP=4 staging), push high-logit candidates
// =====================================================================
__device__ __forceinline__ void dec_process(float4 v, int i, int b, int a0) {
    int la   = i / 21;
    int col0 = (i - la * 21) * 4;
    int a    = a0 + la;
    float xs[4] = { v.x, v.y, v.z, v.w };
#pragma unroll
    for (int j = 0; j < 4; ++j) {
        float x = xs[j];
        int col = col0 + j;
        if (col >= 4 && x > PUSH_T) {
            int c = col - 4;
            int task = b * NCLS + c;
            float s = 1.0f / (1.0f + expf(-x));
            int idx = atomicAdd(&g_cnt[task * CNTSTR], 1);
            if (idx < CCAP) {
                unsigned key = __float_as_uint(s) | 0x80000000u;
                g_cand[(size_t)task * CCAP + idx] =
                    ((unsigned long long)key << 32) | (unsigned)(~(unsigned)a);
            }
        }
    }
}

__global__ void __launch_bounds__(256) k_decode(const float* __restrict__ pred) {
    const int nT = 600;
    const int b  = blockIdx.x / nT;
    const int t  = blockIdx.x % nT;
    const int a0 = t << 7;
    const int na = min(128, A_N - a0);
    const float4* src = (const float4*)(pred + ((size_t)b * A_N + a0) * 84);
    const int tid = threadIdx.x;
    const int tot = na * 21;                      // 2688 for full tiles

    int base = 0;
    for (; base + 1024 <= tot; base += 1024) {    // unroll-4: 4 independent LDG.128
        float4 v0 = src[base + tid];
        float4 v1 = src[base + tid + 256];
        float4 v2 = src[base + tid + 512];
        float4 v3 = src[base + tid + 768];
        dec_process(v0, base + tid,       b, a0);
        dec_process(v1, base + tid + 256, b, a0);
        dec_process(v2, base + tid + 512, b, a0);
        dec_process(v3, base + tid + 768, b, a0);
    }
    {   // tail: 640 float4 = 2.5 strides (two staged + predicated third)
        int i0 = base + tid, i1 = i0 + 256, i2 = i1 + 256;
        float4 v0, v1, v2;
        bool p0 = i0 < tot, p1 = i1 < tot, p2 = i2 < tot;
        if (p0) v0 = src[i0];
        if (p1) v1 = src[i1];
        if (p2) v2 = src[i2];
        if (p0) dec_process(v0, i0, b, a0);
        if (p1) dec_process(v1, i1, b, a0);
        if (p2) dec_process(v2, i2, b, a0);
    }
}

// =====================================================================
// Kernel 2: per (b,c) exact top-256 + greedy NMS + per-class top-100
// =====================================================================
__global__ void __launch_bounds__(256, 6) k_select(const float* __restrict__ pred,
                                                   const float* __restrict__ anchors) {
    extern __shared__ unsigned char sm[];
    unsigned*           hist = (unsigned*)sm;                      // 8KB
    unsigned*           csum = (unsigned*)(sm + 8192);
    int*                ctrl = (int*)(sm + 9232);
    unsigned long long* BUF  = (unsigned long long*)(sm + 9728);   // 8KB

    const int tid  = threadIdx.x;
    const int task = blockIdx.x;
    const int b    = task / NCLS;
    const int c    = task % NCLS;

    const int n = g_cnt[task * CNTSTR];
    bool fallback = !(n >= KPRE && n <= CCAP);
    const unsigned long long* cand = g_cand + (size_t)task * CCAP;

    for (int i = tid; i < NBIN2; i += 256) hist[i] = 0;
    if (tid < 8) ctrl[tid] = 0;
    __syncthreads();

    if (!fallback) {
        for (int i = tid; i < n; i += 256) {
            unsigned key = (unsigned)(cand[i] >> 32);
            atomicAdd(&hist[(key - SEL_BASE) >> 10], 1u);
        }
        __syncthreads();
        (void)suffix_total<8>(hist, csum, tid);
        crossing<8>(hist, csum, ctrl, KPRE, tid);
        const unsigned B1 = (unsigned)ctrl[0];
        const unsigned C1 = (unsigned)ctrl[1];
        const unsigned need = C1 + hist[B1];
        __syncthreads();

        if (need <= (unsigned)BUFN) {
            const unsigned minKey = SEL_BASE + (B1 << 10);
            if (tid == 0) ctrl[2] = 0;
            __syncthreads();
            for (int i = tid; i < n; i += 256) {
                unsigned long long e = cand[i];
                if ((unsigned)(e >> 32) >= minKey) {
                    int p = atomicAdd(&ctrl[2], 1);
                    BUF[p] = e;
                }
            }
            __syncthreads();
        } else {
            fallback = true;
        }
    }

    if (fallback) {
        for (int i = tid; i < NBIN2; i += 256) hist[i] = 0;
        if (tid < 8) ctrl[tid] = 0;
        __syncthreads();
        unsigned cnt = 0;
        for (int a = tid; a < A_N; a += 256) {
            float x = pred[((size_t)b * A_N + a) * 84 + 4 + c];
            float s = 1.0f / (1.0f + expf(-x));
            if (s > 0.05f) { ++cnt; atomicAdd(&hist[fkey32(s) >> 21], 1u); }
        }
        for (int o = 16; o; o >>= 1) cnt += __shfl_down_sync(0xFFFFFFFFu, cnt, o);
        if ((tid & 31) == 0) atomicAdd((unsigned*)&ctrl[5], cnt);
        __syncthreads();
        const unsigned total = (unsigned)ctrl[5];
        if (total == 0u) {
            for (int p = tid; p < MDPC; p += 256) {
                g_cls_scores[task * MDPC + p] = -1.0f;
                g_cls_boxes [task * MDPC + p] = make_float4(0.f, 0.f, 0.f, 0.f);
            }
            return;
        }
        const unsigned target = total < (unsigned)KPRE ? total : (unsigned)KPRE;
        (void)suffix_total<8>(hist, csum, tid);
        crossing<8>(hist, csum, ctrl, target, tid);
        const unsigned B1 = (unsigned)ctrl[0];
        const unsigned C1 = (unsigned)ctrl[1];
        __syncthreads();
        for (int i = tid; i < NBIN2; i += 256) hist[i] = 0;
        __syncthreads();
        for (int a = tid; a < A_N; a += 256) {
            float x = pred[((size_t)b * A_N + a) * 84 + 4 + c];
            float s = 1.0f / (1.0f + expf(-x));
            if (s > 0.05f) {
                unsigned key = fkey32(s);
                if ((key >> 21) == B1) atomicAdd(&hist[(key >> 10) & 0x7FFu], 1u);
            }
        }
        __syncthreads();
        (void)suffix_total<8>(hist, csum, tid);
        crossing<8>(hist, csum, ctrl, target - C1, tid);
        const unsigned B2 = (unsigned)ctrl[0];
        if (tid == 0) ctrl[2] = 0;
        __syncthreads();
        for (int a = tid; a < A_N; a += 256) {
            float x = pred[((size_t)b * A_N + a) * 84 + 4 + c];
            float s = 1.0f / (1.0f + expf(-x));
            if (s > 0.05f) {
                unsigned key = fkey32(s);
                unsigned l1 = key >> 21;
                bool take = l1 > B1 || (l1 == B1 && ((key >> 10) & 0x7FFu) >= B2);
                if (take) {
                    int p = atomicAdd(&ctrl[2], 1);
                    if (p < BUFN)
                        BUF[p] = ((unsigned long long)key << 32) | (unsigned)(~(unsigned)a);
                }
            }
        }
        __syncthreads();
    }

    int sel = ctrl[2]; if (sel > BUFN) sel = BUFN;
    const int W = (sel <= 512) ? 512 : 1024;
    for (int i = sel + tid; i < W; i += 256) BUF[i] = 0ull;
    __syncthreads();

    for (int kk = 2; kk <= W; kk <<= 1) {
        for (int j = kk >> 1; j > 0; j >>= 1) {
            for (int i = tid; i < W; i += 256) {
                int ix = i ^ j;
                if (ix > i) {
                    unsigned long long x = BUF[i], y = BUF[ix];
                    bool sw = ((i & kk) == 0) ? (x < y) : (x > y);
                    if (sw) { BUF[i] = y; BUF[ix] = x; }
                }
            }
            __syncthreads();
        }
    }

    // ---- NMS on top-256 ----
    float*    X1    = (float*)sm;
    float*    Y1    = (float*)(sm + 1024);
    float*    X2    = (float*)(sm + 2048);
    float*    Y2    = (float*)(sm + 3072);
    float*    AR    = (float*)(sm + 4096);
    float*    SC    = (float*)(sm + 5120);
    unsigned* MASKS = (unsigned*)(sm + 6144);
    unsigned* KEEPW = (unsigned*)(sm + 14336);
    unsigned* WPFX  = (unsigned*)(sm + 14400);

    {
        unsigned long long e = BUF[tid];
        unsigned key  = (unsigned)(e >> 32);
        unsigned aidx = ~(unsigned)(e & 0xFFFFFFFFull);
        float  s  = -1.0f;
        float4 bx = make_float4(0.f, 0.f, 0.f, 0.f);
        if (key) {
            const float4 bp = *(const float4*)(pred + ((size_t)b * A_N + aidx) * 84);
            const float4 an = ((const float4*)anchors)[aidx];
            float cx = bp.x * 0.1f * an.z + an.x;
            float cy = bp.y * 0.1f * an.w + an.y;
            float w  = expf(bp.z * 0.2f) * an.z;
            float h  = expf(bp.w * 0.2f) * an.w;
            bx = make_float4(cx - w * 0.5f, cy - h * 0.5f, cx + w * 0.5f, cy + h * 0.5f);
            s  = __uint_as_float(key & 0x7FFFFFFFu);
        }
        X1[tid] = bx.x; Y1[tid] = bx.y; X2[tid] = bx.z; Y2[tid] = bx.w;
        AR[tid] = (bx.z - bx.x) * (bx.w - bx.y);
        SC[tid] = s;
        unsigned bal = __ballot_sync(0xFFFFFFFFu, key != 0u);
        if ((tid & 31) == 0) KEEPW[tid >> 5] = bal;
    }
    __syncthreads();

    {   // triangular suppression mask, divide-free IoU test
        float ax1 = X1[tid], ay1 = Y1[tid], ax2 = X2[tid], ay2 = Y2[tid], aa = AR[tid];
        const int w0 = tid >> 5;
        for (int w = 0; w < w0; ++w) MASKS[tid * 8 + w] = 0u;
        for (int w = w0; w < 8; ++w) {
            unsigned m = 0;
            int l0 = (w == w0) ? (tid & 31) + 1 : 0;
            for (int l = l0; l < 32; ++l) {
                int j = w * 32 + l;
                float iw = fmaxf(fminf(ax2, X2[j]) - fmaxf(ax1, X1[j]), 0.f);
                float ih = fmaxf(fminf(ay2, Y2[j]) - fmaxf(ay1, Y1[j]), 0.f);
                float inter = iw * ih;
                float thr = 0.5f * fmaxf(aa + AR[j] - inter, 1e-8f);
                if (inter > thr) m |= (1u << l);
            }
            MASKS[tid * 8 + w] = m;
        }
    }
    __syncthreads();

    if (tid < 32) {
        unsigned kw = (tid < 8) ? KEEPW[tid] : 0u;
        for (int i = 0; i < 256; ++i) {
            unsigned word = __shfl_sync(0xFFFFFFFFu, kw, i >> 5);
            if ((word >> (i & 31)) & 1u) {
                if (tid < 8) kw &= ~MASKS[i * 8 + tid];
            }
        }
        if (tid < 8) KEEPW[tid] = kw;
    }
    __syncthreads();

    if (tid == 0) {
        unsigned run = 0;
        for (int w = 0; w < 8; ++w) { WPFX[w] = run; run += __popc(KEEPW[w]); }
        WPFX[8] = run;
    }
    __syncthreads();

    {
        unsigned w = tid >> 5, bpos = tid & 31;
        unsigned kwv = KEEPW[w];
        bool kept = (kwv >> bpos) & 1u;
        unsigned p = WPFX[w] + __popc(kwv & ((1u << bpos) - 1u));
        if (kept && p < MDPC) {
            g_cls_scores[task * MDPC + p] = SC[tid];
            g_cls_boxes [task * MDPC + p] = make_float4(X1[tid], Y1[tid], X2[tid], Y2[tid]);
        }
        int kc = (int)WPFX[8];
        for (int q = kc + tid; q < MDPC; q += 256) {
            g_cls_scores[task * MDPC + q] = -1.0f;
            g_cls_boxes [task * MDPC + q] = make_float4(0.f, 0.f, 0.f, 0.f);
        }
    }
}

// =====================================================================
// Kernel 3: per image top-100 of 8000
// =====================================================================
__global__ void __launch_bounds__(256) k_final(float* __restrict__ out) {
    __shared__ unsigned hist[NBINF];
    __shared__ unsigned long long BUF[256];
    __shared__ unsigned csum[257];
    __shared__ int ctrl[8];
    __shared__ int vc;

    const int tid = threadIdx.x;
    const int b   = blockIdx.x;
    const float* sc = g_cls_scores + b * NCLS * MDPC;

    for (int i = tid; i < NBINF; i += 256) hist[i] = 0;
    if (tid < 8) ctrl[tid] = 0;
    __syncthreads();

    unsigned cnt = 0;
    for (int i = tid; i < NCLS * MDPC; i += 256) {
        float s = sc[i];
        if (s > 0.0f) { ++cnt; atomicAdd(&hist[(fkey32(s) - FIN_BASE) >> 14], 1u); }
    }
    for (int o = 16; o; o >>= 1) cnt += __shfl_down_sync(0xFFFFFFFFu, cnt, o);
    if ((tid & 31) == 0) atomicAdd((unsigned*)&ctrl[5], cnt);
    __syncthreads();
    const unsigned npos = (unsigned)ctrl[5];

    if (npos >= (unsigned)MAXD) {
        (void)suffix_total<16>(hist, csum, tid);
        crossing<16>(hist, csum, ctrl, MAXD, tid);
        const unsigned B1 = (unsigned)ctrl[0];
        const unsigned C1 = (unsigned)ctrl[1];
        __syncthreads();
        for (int i = tid; i < NBINF; i += 256) hist[i] = 0;
        __syncthreads();
        for (int i = tid; i < NCLS * MDPC; i += 256) {
            float s = sc[i];
            if (s > 0.0f) {
                unsigned key = fkey32(s);
                if (((key - FIN_BASE) >> 14) == B1) atomicAdd(&hist[(key >> 2) & 0xFFFu], 1u);
            }
        }
        __syncthreads();
        (void)suffix_total<16>(hist, csum, tid);
        crossing<16>(hist, csum, ctrl, MAXD - C1, tid);
        const unsigned B2 = (unsigned)ctrl[0];
        if (tid == 0) ctrl[2] = 0;
        __syncthreads();
        for (int i = tid; i < NCLS * MDPC; i += 256) {
            float s = sc[i];
            if (s > 0.0f) {
                unsigned key = fkey32(s);
                unsigned l1 = (key - FIN_BASE) >> 14;
                bool take = l1 > B1 || (l1 == B1 && ((key >> 2) & 0xFFFu) >= B2);
                if (take) {
                    int p = atomicAdd(&ctrl[2], 1);
                    if (p < 256)
                        BUF[p] = ((unsigned long long)key << 32) | (unsigned)(~(unsigned)i);
                }
            }
        }
        __syncthreads();
    } else {
        if (tid == 0) ctrl[2] = 0;
        __syncthreads();
        for (int i = tid; i < NCLS * MDPC; i += 256) {
            float s = sc[i];
            if (s > 0.0f) {
                int p = atomicAdd(&ctrl[2], 1);
                if (p < 256)
                    BUF[p] = ((unsigned long long)fkey32(s) << 32) | (unsigned)(~(unsigned)i);
            }
        }
        __syncthreads();
    }

    int sel = ctrl[2]; if (sel > 256) sel = 256;
    if (tid >= sel) BUF[tid] = 0ull;
    __syncthreads();

    for (int kk = 2; kk <= 256; kk <<= 1) {
        for (int j = kk >> 1; j > 0; j >>= 1) {
            int ix = tid ^ j;
            if (ix > tid) {
                unsigned long long x = BUF[tid], y = BUF[ix];
                bool sw = ((tid & kk) == 0) ? (x < y) : (x > y);
                if (sw) { BUF[tid] = y; BUF[ix] = x; }
            }
            __syncthreads();
        }
    }

    if (tid == 0) vc = 0;
    __syncthreads();

    if (tid < MAXD) {
        unsigned long long e = BUF[tid];
        unsigned key  = (unsigned)(e >> 32);
        unsigned flat = ~(unsigned)(e & 0xFFFFFFFFull);
        bool valid = (key != 0u);
        float4 bx = make_float4(0.f, 0.f, 0.f, 0.f);
        float cls = 0.0f, so = 0.0f;
        if (valid) {
            float s = __uint_as_float((key & 0x80000000u) ? (key & 0x7FFFFFFFu) : ~key);
            bx  = g_cls_boxes[b * NCLS * MDPC + flat];
            cls = (float)(flat / MDPC);
            so  = s;
            atomicAdd(&vc, 1);
        }
        out[b * 400 + tid * 4 + 0] = bx.x;
        out[b * 400 + tid * 4 + 1] = bx.y;
        out[b * 400 + tid * 4 + 2] = bx.z;
        out[b * 400 + tid * 4 + 3] = bx.w;
        out[NB * MAXD * 4 + b * MAXD + tid]             = so;
        out[NB * MAXD * 4 + NB * MAXD + b * MAXD + tid] = cls;
    }
    __syncthreads();
    if (tid == 0) out[NB * MAXD * 6 + b] = (float)vc;
}

// =====================================================================
extern "C" void kernel_launch(void* const* d_in, const int* in_sizes, int n_in,
                              void* d_out, int out_size) {
    (void)in_sizes; (void)n_in; (void)out_size;
    const float* pred    = (const float*)d_in[1];
    const float* anchors = (const float*)d_in[2];
    float* out = (float*)d_out;

    k_nop<<<1, 32>>>();                      // two nops: ncu window lands on k_decode
    k_nop<<<1, 32>>>();
    k_zero<<<80, 256>>>();
    k_decode<<<NB * 600, 256>>>(pred);

    cudaFuncSetAttribute(k_select, cudaFuncAttributeMaxDynamicSharedMemorySize, 17920);
    k_select<<<NTASK, 256, 17920>>>(pred, anchors);

    k_final<<<NB, 256>>>(out);
}

// round 11
// speedup vs baseline: 4.4996x; 1.0350x over previous
#include <cuda_runtime.h>
#include <math.h>

#define A_N    76725
#define NCLS   80
#define NB     8
#define NTASK  (NB*NCLS)
#define KPRE   256
#define MDPC   100
#define MAXD   100
#define CCAP   3072
#define BUFN   1024
#define NBIN2  2048
#define NBINF  4096
#define PUSH_T 2.5f
#define CNTSTR 32
#define SEL_BASE 0xBF600000u
#define FIN_BASE 0xBD400000u

__device__ unsigned long long g_cand[(size_t)NTASK * CCAP];
__device__ int    g_cnt[NTASK * CNTSTR];
__device__ float  g_cls_scores[NTASK * MDPC];
__device__ float4 g_cls_boxes[NTASK * MDPC];

__device__ __forceinline__ unsigned fkey32(float x) {
    unsigned b = __float_as_uint(x);
    return (b & 0x80000000u) ? ~b : (b | 0x80000000u);
}

template <int BPT>
__device__ __forceinline__ unsigned suffix_total(const unsigned* hist, unsigned* csum, int tid) {
    unsigned s = 0;
    const int base = tid * BPT;
#pragma unroll
    for (int r = 0; r < BPT; ++r) s += hist[base + r];
    csum[tid] = s;
    __syncthreads();
    for (int off = 1; off < 256; off <<= 1) {
        unsigned add = (tid + off < 256) ? csum[tid + off] : 0u;
        __syncthreads();
        csum[tid] += add;
        __syncthreads();
    }
    return csum[0];
}

template <int BPT>
__device__ __forceinline__ void crossing(const unsigned* hist, const unsigned* csum, int* ctrl,
                                         unsigned target, int tid) {
    unsigned run = (tid + 1 < 256) ? csum[tid + 1] : 0u;
    const int base = tid * BPT;
    for (int i = base + BPT - 1; i >= base; --i) {
        unsigned h = hist[i];
        run += h;
        if (run >= target && run - h < target) { ctrl[0] = i; ctrl[1] = (int)(run - h); }
    }
    __syncthreads();
}

// =====================================================================
__global__ void k_nop() {}

__global__ void k_zero() {
    int i = blockIdx.x * 256 + threadIdx.x;
    if (i < NTASK * CNTSTR) g_cnt[i] = 0;
}

// =====================================================================
// Kernel 1: stream predictions; hierarchical threshold test keeps the
// common path at ~6 instructions per float4 (issue ceiling >> DRAM)
// =====================================================================
__device__ __forceinline__ void dec_push(float x, int col, int b, int a) {
    if (col >= 4 && x > PUSH_T) {
        int task = b * NCLS + (col - 4);
        float s = 1.0f / (1.0f + expf(-x));
        int idx = atomicAdd(&g_cnt[task * CNTSTR], 1);
        if (idx < CCAP) {
            unsigned key = __float_as_uint(s) | 0x80000000u;
            g_cand[(size_t)task * CCAP + idx] =
                ((unsigned long long)key << 32) | (unsigned)(~(unsigned)a);
        }
    }
}

__device__ __forceinline__ void dec_process(float4 v, int i, int b, int a0) {
    float m = fmaxf(fmaxf(v.x, v.y), fmaxf(v.z, v.w));
    if (m > PUSH_T) {                       // rare (~2.5% of float4s)
        int la   = i / 21;
        int col0 = (i - la * 21) * 4;
        int a    = a0 + la;
        dec_push(v.x, col0,     b, a);
        dec_push(v.y, col0 + 1, b, a);
        dec_push(v.z, col0 + 2, b, a);
        dec_push(v.w, col0 + 3, b, a);
    }
}

__global__ void __launch_bounds__(256) k_decode(const float* __restrict__ pred) {
    const int nT = 600;
    const int b  = blockIdx.x / nT;
    const int t  = blockIdx.x % nT;
    const int a0 = t << 7;
    const int na = min(128, A_N - a0);
    const float4* src = (const float4*)(pred + ((size_t)b * A_N + a0) * 84);
    const int tid = threadIdx.x;
    const int tot = na * 21;                      // 2688 for full tiles

    int base = 0;
    for (; base + 1024 <= tot; base += 1024) {
        float4 v0 = src[base + tid];
        float4 v1 = src[base + tid + 256];
        float4 v2 = src[base + tid + 512];
        float4 v3 = src[base + tid + 768];
        dec_process(v0, base + tid,       b, a0);
        dec_process(v1, base + tid + 256, b, a0);
        dec_process(v2, base + tid + 512, b, a0);
        dec_process(v3, base + tid + 768, b, a0);
    }
    {
        int i0 = base + tid, i1 = i0 + 256, i2 = i1 + 256;
        float4 v0, v1, v2;
        bool p0 = i0 < tot, p1 = i1 < tot, p2 = i2 < tot;
        if (p0) v0 = src[i0];
        if (p1) v1 = src[i1];
        if (p2) v2 = src[i2];
        if (p0) dec_process(v0, i0, b, a0);
        if (p1) dec_process(v1, i1, b, a0);
        if (p2) dec_process(v2, i2, b, a0);
    }
}

// =====================================================================
// Kernel 2: per (b,c) exact top-256 + greedy NMS + per-class top-100
// =====================================================================
__global__ void __launch_bounds__(256, 6) k_select(const float* __restrict__ pred,
                                                   const float* __restrict__ anchors) {
    extern __shared__ unsigned char sm[];
    unsigned*           hist = (unsigned*)sm;                      // 8KB
    unsigned*           csum = (unsigned*)(sm + 8192);
    int*                ctrl = (int*)(sm + 9232);
    unsigned long long* BUF  = (unsigned long long*)(sm + 9728);   // 8KB

    const int tid  = threadIdx.x;
    const int task = blockIdx.x;
    const int b    = task / NCLS;
    const int c    = task % NCLS;

    const int n = g_cnt[task * CNTSTR];
    bool fallback = !(n >= KPRE && n <= CCAP);
    const unsigned long long* cand = g_cand + (size_t)task * CCAP;

    for (int i = tid; i < NBIN2; i += 256) hist[i] = 0;
    if (tid < 8) ctrl[tid] = 0;
    __syncthreads();

    if (!fallback) {
        for (int i = tid; i < n; i += 256) {
            unsigned key = (unsigned)(cand[i] >> 32);
            atomicAdd(&hist[(key - SEL_BASE) >> 10], 1u);
        }
        __syncthreads();
        (void)suffix_total<8>(hist, csum, tid);
        crossing<8>(hist, csum, ctrl, KPRE, tid);
        const unsigned B1 = (unsigned)ctrl[0];
        const unsigned C1 = (unsigned)ctrl[1];
        const unsigned need = C1 + hist[B1];
        __syncthreads();

        if (need <= (unsigned)BUFN) {
            const unsigned minKey = SEL_BASE + (B1 << 10);
            if (tid == 0) ctrl[2] = 0;
            __syncthreads();
            for (int i = tid; i < n; i += 256) {
                unsigned long long e = cand[i];
                if ((unsigned)(e >> 32) >= minKey) {
                    int p = atomicAdd(&ctrl[2], 1);
                    BUF[p] = e;
                }
            }
            __syncthreads();
        } else {
            fallback = true;
        }
    }

    if (fallback) {
        for (int i = tid; i < NBIN2; i += 256) hist[i] = 0;
        if (tid < 8) ctrl[tid] = 0;
        __syncthreads();
        unsigned cnt = 0;
        for (int a = tid; a < A_N; a += 256) {
            float x = pred[((size_t)b * A_N + a) * 84 + 4 + c];
            float s = 1.0f / (1.0f + expf(-x));
            if (s > 0.05f) { ++cnt; atomicAdd(&hist[fkey32(s) >> 21], 1u); }
        }
        for (int o = 16; o; o >>= 1) cnt += __shfl_down_sync(0xFFFFFFFFu, cnt, o);
        if ((tid & 31) == 0) atomicAdd((unsigned*)&ctrl[5], cnt);
        __syncthreads();
        const unsigned total = (unsigned)ctrl[5];
        if (total == 0u) {
            for (int p = tid; p < MDPC; p += 256) {
                g_cls_scores[task * MDPC + p] = -1.0f;
                g_cls_boxes [task * MDPC + p] = make_float4(0.f, 0.f, 0.f, 0.f);
            }
            return;
        }
        const unsigned target = total < (unsigned)KPRE ? total : (unsigned)KPRE;
        (void)suffix_total<8>(hist, csum, tid);
        crossing<8>(hist, csum, ctrl, target, tid);
        const unsigned B1 = (unsigned)ctrl[0];
        const unsigned C1 = (unsigned)ctrl[1];
        __syncthreads();
        for (int i = tid; i < NBIN2; i += 256) hist[i] = 0;
        __syncthreads();
        for (int a = tid; a < A_N; a += 256) {
            float x = pred[((size_t)b * A_N + a) * 84 + 4 + c];
            float s = 1.0f / (1.0f + expf(-x));
            if (s > 0.05f) {
                unsigned key = fkey32(s);
                if ((key >> 21) == B1) atomicAdd(&hist[(key >> 10) & 0x7FFu], 1u);
            }
        }
        __syncthreads();
        (void)suffix_total<8>(hist, csum, tid);
        crossing<8>(hist, csum, ctrl, target - C1, tid);
        const unsigned B2 = (unsigned)ctrl[0];
        if (tid == 0) ctrl[2] = 0;
        __syncthreads();
        for (int a = tid; a < A_N; a += 256) {
            float x = pred[((size_t)b * A_N + a) * 84 + 4 + c];
            float s = 1.0f / (1.0f + expf(-x));
            if (s > 0.05f) {
                unsigned key = fkey32(s);
                unsigned l1 = key >> 21;
                bool take = l1 > B1 || (l1 == B1 && ((key >> 10) & 0x7FFu) >= B2);
                if (take) {
                    int p = atomicAdd(&ctrl[2], 1);
                    if (p < BUFN)
                        BUF[p] = ((unsigned long long)key << 32) | (unsigned)(~(unsigned)a);
                }
            }
        }
        __syncthreads();
    }

    int sel = ctrl[2]; if (sel > BUFN) sel = BUFN;
    const int W = (sel <= 256) ? 256 : ((sel <= 512) ? 512 : 1024);
    for (int i = sel + tid; i < W; i += 256) BUF[i] = 0ull;
    __syncthreads();

    for (int kk = 2; kk <= W; kk <<= 1) {
        for (int j = kk >> 1; j > 0; j >>= 1) {
            for (int i = tid; i < W; i += 256) {
                int ix = i ^ j;
                if (ix > i) {
                    unsigned long long x = BUF[i], y = BUF[ix];
                    bool sw = ((i & kk) == 0) ? (x < y) : (x > y);
                    if (sw) { BUF[i] = y; BUF[ix] = x; }
                }
            }
            __syncthreads();
        }
    }

    // ---- NMS on top-256 ----
    float*    X1    = (float*)sm;
    float*    Y1    = (float*)(sm + 1024);
    float*    X2    = (float*)(sm + 2048);
    float*    Y2    = (float*)(sm + 3072);
    float*    AR    = (float*)(sm + 4096);
    float*    SC    = (float*)(sm + 5120);
    unsigned* MASKS = (unsigned*)(sm + 6144);
    unsigned* KEEPW = (unsigned*)(sm + 14336);
    unsigned* WPFX  = (unsigned*)(sm + 14400);

    {
        unsigned long long e = BUF[tid];
        unsigned key  = (unsigned)(e >> 32);
        unsigned aidx = ~(unsigned)(e & 0xFFFFFFFFull);
        float  s  = -1.0f;
        float4 bx = make_float4(0.f, 0.f, 0.f, 0.f);
        if (key) {
            const float4 bp = *(const float4*)(pred + ((size_t)b * A_N + aidx) * 84);
            const float4 an = ((const float4*)anchors)[aidx];
            float cx = bp.x * 0.1f * an.z + an.x;
            float cy = bp.y * 0.1f * an.w + an.y;
            float w  = expf(bp.z * 0.2f) * an.z;
            float h  = expf(bp.w * 0.2f) * an.w;
            bx = make_float4(cx - w * 0.5f, cy - h * 0.5f, cx + w * 0.5f, cy + h * 0.5f);
            s  = __uint_as_float(key & 0x7FFFFFFFu);
        }
        X1[tid] = bx.x; Y1[tid] = bx.y; X2[tid] = bx.z; Y2[tid] = bx.w;
        AR[tid] = (bx.z - bx.x) * (bx.w - bx.y);
        SC[tid] = s;
        unsigned bal = __ballot_sync(0xFFFFFFFFu, key != 0u);
        if ((tid & 31) == 0) KEEPW[tid >> 5] = bal;
    }
    __syncthreads();

    {   // triangular suppression mask, divide-free IoU test
        float ax1 = X1[tid], ay1 = Y1[tid], ax2 = X2[tid], ay2 = Y2[tid], aa = AR[tid];
        const int w0 = tid >> 5;
        for (int w = 0; w < w0; ++w) MASKS[tid * 8 + w] = 0u;
        for (int w = w0; w < 8; ++w) {
            unsigned m = 0;
            int l0 = (w == w0) ? (tid & 31) + 1 : 0;
            for (int l = l0; l < 32; ++l) {
                int j = w * 32 + l;
                float iw = fmaxf(fminf(ax2, X2[j]) - fmaxf(ax1, X1[j]), 0.f);
                float ih = fmaxf(fminf(ay2, Y2[j]) - fmaxf(ay1, Y1[j]), 0.f);
                float inter = iw * ih;
                float thr = 0.5f * fmaxf(aa + AR[j] - inter, 1e-8f);
                if (inter > thr) m |= (1u << l);
            }
            MASKS[tid * 8 + w] = m;
        }
    }
    __syncthreads();

    if (tid < 32) {
        unsigned kw = (tid < 8) ? KEEPW[tid] : 0u;
        for (int i = 0; i < 256; ++i) {
            unsigned word = __shfl_sync(0xFFFFFFFFu, kw, i >> 5);
            if ((word >> (i & 31)) & 1u) {
                if (tid < 8) kw &= ~MASKS[i * 8 + tid];
            }
        }
        if (tid < 8) KEEPW[tid] = kw;
    }
    __syncthreads();

    if (tid == 0) {
        unsigned run = 0;
        for (int w = 0; w < 8; ++w) { WPFX[w] = run; run += __popc(KEEPW[w]); }
        WPFX[8] = run;
    }
    __syncthreads();

    {
        unsigned w = tid >> 5, bpos = tid & 31;
        unsigned kwv = KEEPW[w];
        bool kept = (kwv >> bpos) & 1u;
        unsigned p = WPFX[w] + __popc(kwv & ((1u << bpos) - 1u));
        if (kept && p < MDPC) {
            g_cls_scores[task * MDPC + p] = SC[tid];
            g_cls_boxes [task * MDPC + p] = make_float4(X1[tid], Y1[tid], X2[tid], Y2[tid]);
        }
        int kc = (int)WPFX[8];
        for (int q = kc + tid; q < MDPC; q += 256) {
            g_cls_scores[task * MDPC + q] = -1.0f;
            g_cls_boxes [task * MDPC + q] = make_float4(0.f, 0.f, 0.f, 0.f);
        }
    }
}

// =====================================================================
// Kernel 3: per image top-100 of 8000
// =====================================================================
__global__ void __launch_bounds__(256) k_final(float* __restrict__ out) {
    __shared__ unsigned hist[NBINF];
    __shared__ unsigned long long BUF[256];
    __shared__ unsigned csum[257];
    __shared__ int ctrl[8];
    __shared__ int vc;

    const int tid = threadIdx.x;
    const int b   = blockIdx.x;
    const float* sc = g_cls_scores + b * NCLS * MDPC;

    for (int i = tid; i < NBINF; i += 256) hist[i] = 0;
    if (tid < 8) ctrl[tid] = 0;
    __syncthreads();

    unsigned cnt = 0;
    for (int i = tid; i < NCLS * MDPC; i += 256) {
        float s = sc[i];
        if (s > 0.0f) { ++cnt; atomicAdd(&hist[(fkey32(s) - FIN_BASE) >> 14], 1u); }
    }
    for (int o = 16; o; o >>= 1) cnt += __shfl_down_sync(0xFFFFFFFFu, cnt, o);
    if ((tid & 31) == 0) atomicAdd((unsigned*)&ctrl[5], cnt);
    __syncthreads();
    const unsigned npos = (unsigned)ctrl[5];

    if (npos >= (unsigned)MAXD) {
        (void)suffix_total<16>(hist, csum, tid);
        crossing<16>(hist, csum, ctrl, MAXD, tid);
        const unsigned B1 = (unsigned)ctrl[0];
        const unsigned C1 = (unsigned)ctrl[1];
        __syncthreads();
        for (int i = tid; i < NBINF; i += 256) hist[i] = 0;
        __syncthreads();
        for (int i = tid; i < NCLS * MDPC; i += 256) {
            float s = sc[i];
            if (s > 0.0f) {
                unsigned key = fkey32(s);
                if (((key - FIN_BASE) >> 14) == B1) atomicAdd(&hist[(key >> 2) & 0xFFFu], 1u);
            }
        }
        __syncthreads();
        (void)suffix_total<16>(hist, csum, tid);
        crossing<16>(hist, csum, ctrl, MAXD - C1, tid);
        const unsigned B2 = (unsigned)ctrl[0];
        if (tid == 0) ctrl[2] = 0;
        __syncthreads();
        for (int i = tid; i < NCLS * MDPC; i += 256) {
            float s = sc[i];
            if (s > 0.0f) {
                unsigned key = fkey32(s);
                unsigned l1 = (key - FIN_BASE) >> 14;
                bool take = l1 > B1 || (l1 == B1 && ((key >> 2) & 0xFFFu) >= B2);
                if (take) {
                    int p = atomicAdd(&ctrl[2], 1);
                    if (p < 256)
                        BUF[p] = ((unsigned long long)key << 32) | (unsigned)(~(unsigned)i);
                }
            }
        }
        __syncthreads();
    } else {
        if (tid == 0) ctrl[2] = 0;
        __syncthreads();
        for (int i = tid; i < NCLS * MDPC; i += 256) {
            float s = sc[i];
            if (s > 0.0f) {
                int p = atomicAdd(&ctrl[2], 1);
                if (p < 256)
                    BUF[p] = ((unsigned long long)fkey32(s) << 32) | (unsigned)(~(unsigned)i);
            }
        }
        __syncthreads();
    }

    int sel = ctrl[2]; if (sel > 256) sel = 256;
    if (tid >= sel) BUF[tid] = 0ull;
    __syncthreads();

    for (int kk = 2; kk <= 256; kk <<= 1) {
        for (int j = kk >> 1; j > 0; j >>= 1) {
            int ix = tid ^ j;
            if (ix > tid) {
                unsigned long long x = BUF[tid], y = BUF[ix];
                bool sw = ((tid & kk) == 0) ? (x < y) : (x > y);
                if (sw) { BUF[tid] = y; BUF[ix] = x; }
            }
            __syncthreads();
        }
    }

    if (tid == 0) vc = 0;
    __syncthreads();

    if (tid < MAXD) {
        unsigned long long e = BUF[tid];
        unsigned key  = (unsigned)(e >> 32);
        unsigned flat = ~(unsigned)(e & 0xFFFFFFFFull);
        bool valid = (key != 0u);
        float4 bx = make_float4(0.f, 0.f, 0.f, 0.f);
        float cls = 0.0f, so = 0.0f;
        if (valid) {
            float s = __uint_as_float((key & 0x80000000u) ? (key & 0x7FFFFFFFu) : ~key);
            bx  = g_cls_boxes[b * NCLS * MDPC + flat];
            cls = (float)(flat / MDPC);
            so  = s;
            atomicAdd(&vc, 1);
        }
        out[b * 400 + tid * 4 + 0] = bx.x;
        out[b * 400 + tid * 4 + 1] = bx.y;
        out[b * 400 + tid * 4 + 2] = bx.z;
        out[b * 400 + tid * 4 + 3] = bx.w;
        out[NB * MAXD * 4 + b * MAXD + tid]             = so;
        out[NB * MAXD * 4 + NB * MAXD + b * MAXD + tid] = cls;
    }
    __syncthreads();
    if (tid == 0) out[NB * MAXD * 6 + b] = (float)vc;
}

// =====================================================================
extern "C" void kernel_launch(void* const* d_in, const int* in_sizes, int n_in,
                              void* d_out, int out_size) {
    (void)in_sizes; (void)n_in; (void)out_size;
    const float* pred    = (const float*)d_in[1];
    const float* anchors = (const float*)d_in[2];
    float* out = (float*)d_out;

    k_nop<<<1, 32>>>();                      // ncu window lands on k_select
    k_zero<<<80, 256>>>();
    k_decode<<<NB * 600, 256>>>(pred);

    cudaFuncSetAttribute(k_select, cudaFuncAttributeMaxDynamicSharedMemorySize, 17920);
    k_select<<<NTASK, 256, 17920>>>(pred, anchors);

    k_final<<<NB, 256>>>(out);
}

// round 12
// speedup vs baseline: 4.7302x; 1.0512x over previous
#include <cuda_runtime.h>
#include <math.h>

#define A_N    76725
#define NCLS   80
#define NB     8
#define NTASK  (NB*NCLS)
#define KPRE   256
#define MDPC   100
#define MAXD   100
#define CCAP   3072
#define BUFN   1024
#define NBIN2  2048
#define NBINF  4096
#define PUSH_T 2.5f
#define CNTSTR 32
#define SEL_BASE 0xBF600000u
#define FIN_BASE 0xBD400000u

__device__ unsigned long long g_cand[(size_t)NTASK * CCAP];
__device__ int    g_cnt[NTASK * CNTSTR];
__device__ float  g_cls_scores[NTASK * MDPC];
__device__ float4 g_cls_boxes[NTASK * MDPC];

__device__ __forceinline__ unsigned fkey32(float x) {
    unsigned b = __float_as_uint(x);
    return (b & 0x80000000u) ? ~b : (b | 0x80000000u);
}

// legacy barrier-scan (used in rarely-taken fallback + k_final)
template <int BPT>
__device__ __forceinline__ unsigned suffix_total(const unsigned* hist, unsigned* csum, int tid) {
    unsigned s = 0;
    const int base = tid * BPT;
#pragma unroll
    for (int r = 0; r < BPT; ++r) s += hist[base + r];
    csum[tid] = s;
    __syncthreads();
    for (int off = 1; off < 256; off <<= 1) {
        unsigned add = (tid + off < 256) ? csum[tid + off] : 0u;
        __syncthreads();
        csum[tid] += add;
        __syncthreads();
    }
    return csum[0];
}

template <int BPT>
__device__ __forceinline__ void crossing(const unsigned* hist, const unsigned* csum, int* ctrl,
                                         unsigned target, int tid) {
    unsigned run = (tid + 1 < 256) ? csum[tid + 1] : 0u;
    const int base = tid * BPT;
    for (int i = base + BPT - 1; i >= base; --i) {
        unsigned h = hist[i];
        run += h;
        if (run >= target && run - h < target) { ctrl[0] = i; ctrl[1] = (int)(run - h); }
    }
    __syncthreads();
}

// shuffle-based inclusive suffix over 256 per-thread sums; 2 barriers total.
// returns suffix-inclusive sum from tid; wtot must hold >=9 u32.
__device__ __forceinline__ unsigned suffix_scan(unsigned s, int tid, volatile unsigned* wtot) {
    unsigned v = s;
    const int lane = tid & 31;
#pragma unroll
    for (int off = 1; off < 32; off <<= 1) {
        unsigned t = __shfl_down_sync(0xFFFFFFFFu, v, off);
        if (lane + off < 32) v += t;
    }
    const int w = tid >> 5;
    if (lane == 0) wtot[w] = v;
    __syncthreads();
    if (tid == 0) {
        unsigned run = 0;
        for (int i = 7; i >= 0; --i) { unsigned t2 = wtot[i]; wtot[i] = run; run += t2; }
        wtot[8] = run;
    }
    __syncthreads();
    return v + wtot[w];
}

__device__ __forceinline__ void crossing2(const unsigned* hist, unsigned runstart, int* ctrl,
                                          unsigned target, int tid) {
    unsigned run = runstart;
    const int base = tid * 8;
#pragma unroll
    for (int i = base + 7; i >= base; --i) {
        unsigned h = hist[i];
        run += h;
        if (run >= target && run - h < target) { ctrl[0] = i; ctrl[1] = (int)(run - h); }
    }
    __syncthreads();
}

// =====================================================================
__global__ void k_nop() {}

__global__ void k_zero() {
    int i = blockIdx.x * 256 + threadIdx.x;
    if (i < NTASK * CNTSTR) g_cnt[i] = 0;
}

// =====================================================================
// Kernel 1: stream predictions; hierarchical threshold test
// =====================================================================
__device__ __forceinline__ void dec_push(float x, int col, int b, int a) {
    if (col >= 4 && x > PUSH_T) {
        int task = b * NCLS + (col - 4);
        float s = 1.0f / (1.0f + expf(-x));
        int idx = atomicAdd(&g_cnt[task * CNTSTR], 1);
        if (idx < CCAP) {
            unsigned key = __float_as_uint(s) | 0x80000000u;
            g_cand[(size_t)task * CCAP + idx] =
                ((unsigned long long)key << 32) | (unsigned)(~(unsigned)a);
        }
    }
}

__device__ __forceinline__ void dec_process(float4 v, int i, int b, int a0) {
    float m = fmaxf(fmaxf(v.x, v.y), fmaxf(v.z, v.w));
    if (m > PUSH_T) {
        int la   = i / 21;
        int col0 = (i - la * 21) * 4;
        int a    = a0 + la;
        dec_push(v.x, col0,     b, a);
        dec_push(v.y, col0 + 1, b, a);
        dec_push(v.z, col0 + 2, b, a);
        dec_push(v.w, col0 + 3, b, a);
    }
}

__global__ void __launch_bounds__(256) k_decode(const float* __restrict__ pred) {
    const int nT = 600;
    const int b  = blockIdx.x / nT;
    const int t  = blockIdx.x % nT;
    const int a0 = t << 7;
    const int na = min(128, A_N - a0);
    const float4* src = (const float4*)(pred + ((size_t)b * A_N + a0) * 84);
    const int tid = threadIdx.x;
    const int tot = na * 21;

    int base = 0;
    for (; base + 1024 <= tot; base += 1024) {
        float4 v0 = src[base + tid];
        float4 v1 = src[base + tid + 256];
        float4 v2 = src[base + tid + 512];
        float4 v3 = src[base + tid + 768];
        dec_process(v0, base + tid,       b, a0);
        dec_process(v1, base + tid + 256, b, a0);
        dec_process(v2, base + tid + 512, b, a0);
        dec_process(v3, base + tid + 768, b, a0);
    }
    {
        int i0 = base + tid, i1 = i0 + 256, i2 = i1 + 256;
        float4 v0, v1, v2;
        bool p0 = i0 < tot, p1 = i1 < tot, p2 = i2 < tot;
        if (p0) v0 = src[i0];
        if (p1) v1 = src[i1];
        if (p2) v2 = src[i2];
        if (p0) dec_process(v0, i0, b, a0);
        if (p1) dec_process(v1, i1, b, a0);
        if (p2) dec_process(v2, i2, b, a0);
    }
}

// =====================================================================
// Kernel 2: per (b,c) exact top-256 + greedy NMS + per-class top-100
// =====================================================================
__global__ void __launch_bounds__(256, 6) k_select(const float* __restrict__ pred,
                                                   const float* __restrict__ anchors) {
    extern __shared__ unsigned char sm[];
    unsigned*           hist = (unsigned*)sm;                      // 8KB
    unsigned*           csum = (unsigned*)(sm + 8192);             // 257 u32 (fallback)
    int*                ctrl = (int*)(sm + 9232);
    unsigned long long* BUF  = (unsigned long long*)(sm + 9728);   // 8KB

    const int tid  = threadIdx.x;
    const int task = blockIdx.x;
    const int b    = task / NCLS;
    const int c    = task % NCLS;

    const int n = g_cnt[task * CNTSTR];
    bool fallback = !(n >= KPRE && n <= CCAP);
    const unsigned long long* cand = g_cand + (size_t)task * CCAP;

    for (int i = tid; i < NBIN2; i += 256) hist[i] = 0;
    if (tid < 8) ctrl[tid] = 0;
    __syncthreads();

    if (!fallback) {
        for (int i = tid; i < n; i += 256) {
            unsigned key = (unsigned)(cand[i] >> 32);
            atomicAdd(&hist[(key - SEL_BASE) >> 10], 1u);
        }
        __syncthreads();
        unsigned s8 = 0;
        {
            const int base = tid * 8;
#pragma unroll
            for (int r = 0; r < 8; ++r) s8 += hist[base + r];
        }
        unsigned incl = suffix_scan(s8, tid, csum);
        crossing2(hist, incl - s8, ctrl, KPRE, tid);
        const unsigned B1 = (unsigned)ctrl[0];
        const unsigned C1 = (unsigned)ctrl[1];
        const unsigned need = C1 + hist[B1];
        __syncthreads();

        if (need <= (unsigned)BUFN) {
            const unsigned minKey = SEL_BASE + (B1 << 10);
            if (tid == 0) ctrl[2] = 0;
            __syncthreads();
            for (int i = tid; i < n; i += 256) {
                unsigned long long e = cand[i];
                if ((unsigned)(e >> 32) >= minKey) {
                    int p = atomicAdd(&ctrl[2], 1);
                    BUF[p] = e;
                }
            }
            __syncthreads();
        } else {
            fallback = true;
        }
    }

    if (fallback) {
        for (int i = tid; i < NBIN2; i += 256) hist[i] = 0;
        if (tid < 8) ctrl[tid] = 0;
        __syncthreads();
        unsigned cnt = 0;
        for (int a = tid; a < A_N; a += 256) {
            float x = pred[((size_t)b * A_N + a) * 84 + 4 + c];
            float s = 1.0f / (1.0f + expf(-x));
            if (s > 0.05f) { ++cnt; atomicAdd(&hist[fkey32(s) >> 21], 1u); }
        }
        for (int o = 16; o; o >>= 1) cnt += __shfl_down_sync(0xFFFFFFFFu, cnt, o);
        if ((tid & 31) == 0) atomicAdd((unsigned*)&ctrl[5], cnt);
        __syncthreads();
        const unsigned total = (unsigned)ctrl[5];
        if (total == 0u) {
            for (int p = tid; p < MDPC; p += 256) {
                g_cls_scores[task * MDPC + p] = -1.0f;
                g_cls_boxes [task * MDPC + p] = make_float4(0.f, 0.f, 0.f, 0.f);
            }
            return;
        }
        const unsigned target = total < (unsigned)KPRE ? total : (unsigned)KPRE;
        (void)suffix_total<8>(hist, csum, tid);
        crossing<8>(hist, csum, ctrl, target, tid);
        const unsigned B1 = (unsigned)ctrl[0];
        const unsigned C1 = (unsigned)ctrl[1];
        __syncthreads();
        for (int i = tid; i < NBIN2; i += 256) hist[i] = 0;
        __syncthreads();
        for (int a = tid; a < A_N; a += 256) {
            float x = pred[((size_t)b * A_N + a) * 84 + 4 + c];
            float s = 1.0f / (1.0f + expf(-x));
            if (s > 0.05f) {
                unsigned key = fkey32(s);
                if ((key >> 21) == B1) atomicAdd(&hist[(key >> 10) & 0x7FFu], 1u);
            }
        }
        __syncthreads();
        (void)suffix_total<8>(hist, csum, tid);
        crossing<8>(hist, csum, ctrl, target - C1, tid);
        const unsigned B2 = (unsigned)ctrl[0];
        if (tid == 0) ctrl[2] = 0;
        __syncthreads();
        for (int a = tid; a < A_N; a += 256) {
            float x = pred[((size_t)b * A_N + a) * 84 + 4 + c];
            float s = 1.0f / (1.0f + expf(-x));
            if (s > 0.05f) {
                unsigned key = fkey32(s);
                unsigned l1 = key >> 21;
                bool take = l1 > B1 || (l1 == B1 && ((key >> 10) & 0x7FFu) >= B2);
                if (take) {
                    int p = atomicAdd(&ctrl[2], 1);
                    if (p < BUFN)
                        BUF[p] = ((unsigned long long)key << 32) | (unsigned)(~(unsigned)a);
                }
            }
        }
        __syncthreads();
    }

    int sel = ctrl[2]; if (sel > BUFN) sel = BUFN;
    const int W = (sel <= 256) ? 256 : ((sel <= 512) ? 512 : 1024);
    for (int i = sel + tid; i < W; i += 256) BUF[i] = 0ull;
    __syncthreads();

    for (int kk = 2; kk <= W; kk <<= 1) {
        for (int j = kk >> 1; j > 0; j >>= 1) {
            for (int i = tid; i < W; i += 256) {
                int ix = i ^ j;
                if (ix > i) {
                    unsigned long long x = BUF[i], y = BUF[ix];
                    bool sw = ((i & kk) == 0) ? (x < y) : (x > y);
                    if (sw) { BUF[i] = y; BUF[ix] = x; }
                }
            }
            __syncthreads();
        }
    }

    // ---- NMS on top-256 ----
    float*    X1    = (float*)sm;
    float*    Y1    = (float*)(sm + 1024);
    float*    X2    = (float*)(sm + 2048);
    float*    Y2    = (float*)(sm + 3072);
    float*    AR    = (float*)(sm + 4096);
    float*    SC    = (float*)(sm + 5120);
    unsigned* MASKS = (unsigned*)(sm + 6144);    // [256][8]
    unsigned* KEEPW = (unsigned*)(sm + 14336);
    unsigned* WPFX  = (unsigned*)(sm + 14400);

    float ax1, ay1, ax2, ay2, aa;
    {
        unsigned long long e = BUF[tid];
        unsigned key  = (unsigned)(e >> 32);
        unsigned aidx = ~(unsigned)(e & 0xFFFFFFFFull);
        float  s  = -1.0f;
        float4 bx = make_float4(0.f, 0.f, 0.f, 0.f);
        if (key) {
            const float4 bp = *(const float4*)(pred + ((size_t)b * A_N + aidx) * 84);
            const float4 an = ((const float4*)anchors)[aidx];
            float cx = bp.x * 0.1f * an.z + an.x;
            float cy = bp.y * 0.1f * an.w + an.y;
            float w  = expf(bp.z * 0.2f) * an.z;
            float h  = expf(bp.w * 0.2f) * an.w;
            bx = make_float4(cx - w * 0.5f, cy - h * 0.5f, cx + w * 0.5f, cy + h * 0.5f);
            s  = __uint_as_float(key & 0x7FFFFFFFu);
        }
        X1[tid] = bx.x; Y1[tid] = bx.y; X2[tid] = bx.z; Y2[tid] = bx.w;
        ax1 = bx.x; ay1 = bx.y; ax2 = bx.z; ay2 = bx.w;
        aa  = (bx.z - bx.x) * (bx.w - bx.y);
        AR[tid] = aa;
        SC[tid] = s;
        unsigned bal = __ballot_sync(0xFFFFFFFFu, key != 0u);
        if ((tid & 31) == 0) KEEPW[tid >> 5] = bal;
#pragma unroll
        for (int w = 0; w < 8; ++w) MASKS[tid * 8 + w] = 0u;
    }
    __syncthreads();

    {   // balanced all-pairs mask: wrapped pairing, 128 uniform iterations
        for (int k = 1; k <= 128; ++k) {
            if (k == 128 && tid >= 128) break;
            int j = (tid + k) & 255;
            float iw = fmaxf(fminf(ax2, X2[j]) - fmaxf(ax1, X1[j]), 0.f);
            float ih = fmaxf(fminf(ay2, Y2[j]) - fmaxf(ay1, Y1[j]), 0.f);
            float inter = iw * ih;
            float thr = 0.5f * fmaxf(aa + AR[j] - inter, 1e-8f);
            if (inter > thr) {
                int lo = tid < j ? tid : j;
                int hi = tid ^ j ^ lo;
                atomicOr(&MASKS[lo * 8 + (hi >> 5)], 1u << (hi & 31));
            }
        }
    }
    __syncthreads();

    if (tid < 32) {   // greedy pass with early exit at 100 keepers
        unsigned kw = (tid < 8) ? KEEPW[tid] : 0u;
        int kcnt = 0;
        for (int i = 0; i < 256 && kcnt < MDPC; ++i) {
            unsigned word = __shfl_sync(0xFFFFFFFFu, kw, i >> 5);
            if ((word >> (i & 31)) & 1u) {
                ++kcnt;
                if (tid < 8) kw &= ~MASKS[i * 8 + tid];
            }
        }
        if (tid < 8) KEEPW[tid] = kw;
    }
    __syncthreads();

    if (tid == 0) {
        unsigned run = 0;
        for (int w = 0; w < 8; ++w) { WPFX[w] = run; run += __popc(KEEPW[w]); }
        WPFX[8] = run;
    }
    __syncthreads();

    {
        unsigned w = tid >> 5, bpos = tid & 31;
        unsigned kwv = KEEPW[w];
        bool kept = (kwv >> bpos) & 1u;
        unsigned p = WPFX[w] + __popc(kwv & ((1u << bpos) - 1u));
        if (kept && p < MDPC) {
            g_cls_scores[task * MDPC + p] = SC[tid];
            g_cls_boxes [task * MDPC + p] = make_float4(X1[tid], Y1[tid], X2[tid], Y2[tid]);
        }
        int kc = (int)WPFX[8];
        for (int q = kc + tid; q < MDPC; q += 256) {
            g_cls_scores[task * MDPC + q] = -1.0f;
            g_cls_boxes [task * MDPC + q] = make_float4(0.f, 0.f, 0.f, 0.f);
        }
    }
}

// =====================================================================
// Kernel 3: per image top-100 of 8000
// =====================================================================
__global__ void __launch_bounds__(256) k_final(float* __restrict__ out) {
    __shared__ unsigned hist[NBINF];
    __shared__ unsigned long long BUF[256];
    __shared__ unsigned csum[257];
    __shared__ int ctrl[8];
    __shared__ int vc;

    const int tid = threadIdx.x;
    const int b   = blockIdx.x;
    const float* sc = g_cls_scores + b * NCLS * MDPC;

    for (int i = tid; i < NBINF; i += 256) hist[i] = 0;
    if (tid < 8) ctrl[tid] = 0;
    __syncthreads();

    unsigned cnt = 0;
    for (int i = tid; i < NCLS * MDPC; i += 256) {
        float s = sc[i];
        if (s > 0.0f) { ++cnt; atomicAdd(&hist[(fkey32(s) - FIN_BASE) >> 14], 1u); }
    }
    for (int o = 16; o; o >>= 1) cnt += __shfl_down_sync(0xFFFFFFFFu, cnt, o);
    if ((tid & 31) == 0) atomicAdd((unsigned*)&ctrl[5], cnt);
    __syncthreads();
    const unsigned npos = (unsigned)ctrl[5];

    if (npos >= (unsigned)MAXD) {
        (void)suffix_total<16>(hist, csum, tid);
        crossing<16>(hist, csum, ctrl, MAXD, tid);
        const unsigned B1 = (unsigned)ctrl[0];
        const unsigned C1 = (unsigned)ctrl[1];
        __syncthreads();
        for (int i = tid; i < NBINF; i += 256) hist[i] = 0;
        __syncthreads();
        for (int i = tid; i < NCLS * MDPC; i += 256) {
            float s = sc[i];
            if (s > 0.0f) {
                unsigned key = fkey32(s);
                if (((key - FIN_BASE) >> 14) == B1) atomicAdd(&hist[(key >> 2) & 0xFFFu], 1u);
            }
        }
        __syncthreads();
        (void)suffix_total<16>(hist, csum, tid);
        crossing<16>(hist, csum, ctrl, MAXD - C1, tid);
        const unsigned B2 = (unsigned)ctrl[0];
        if (tid == 0) ctrl[2] = 0;
        __syncthreads();
        for (int i = tid; i < NCLS * MDPC; i += 256) {
            float s = sc[i];
            if (s > 0.0f) {
                unsigned key = fkey32(s);
                unsigned l1 = (key - FIN_BASE) >> 14;
                bool take = l1 > B1 || (l1 == B1 && ((key >> 2) & 0xFFFu) >= B2);
                if (take) {
                    int p = atomicAdd(&ctrl[2], 1);
                    if (p < 256)
                        BUF[p] = ((unsigned long long)key << 32) | (unsigned)(~(unsigned)i);
                }
            }
        }
        __syncthreads();
    } else {
        if (tid == 0) ctrl[2] = 0;
        __syncthreads();
        for (int i = tid; i < NCLS * MDPC; i += 256) {
            float s = sc[i];
            if (s > 0.0f) {
                int p = atomicAdd(&ctrl[2], 1);
                if (p < 256)
                    BUF[p] = ((unsigned long long)fkey32(s) << 32) | (unsigned)(~(unsigned)i);
            }
        }
        __syncthreads();
    }

    int sel = ctrl[2]; if (sel > 256) sel = 256;
    if (tid >= sel) BUF[tid] = 0ull;
    __syncthreads();

    for (int kk = 2; kk <= 256; kk <<= 1) {
        for (int j = kk >> 1; j > 0; j >>= 1) {
            int ix = tid ^ j;
            if (ix > tid) {
                unsigned long long x = BUF[tid], y = BUF[ix];
                bool sw = ((tid & kk) == 0) ? (x < y) : (x > y);
                if (sw) { BUF[tid] = y; BUF[ix] = x; }
            }
            __syncthreads();
        }
    }

    if (tid == 0) vc = 0;
    __syncthreads();

    if (tid < MAXD) {
        unsigned long long e = BUF[tid];
        unsigned key  = (unsigned)(e >> 32);
        unsigned flat = ~(unsigned)(e & 0xFFFFFFFFull);
        bool valid = (key != 0u);
        float4 bx = make_float4(0.f, 0.f, 0.f, 0.f);
        float cls = 0.0f, so = 0.0f;
        if (valid) {
            float s = __uint_as_float((key & 0x80000000u) ? (key & 0x7FFFFFFFu) : ~key);
            bx  = g_cls_boxes[b * NCLS * MDPC + flat];
            cls = (float)(flat / MDPC);
            so  = s;
            atomicAdd(&vc, 1);
        }
        out[b * 400 + tid * 4 + 0] = bx.x;
        out[b * 400 + tid * 4 + 1] = bx.y;
        out[b * 400 + tid * 4 + 2] = bx.z;
        out[b * 400 + tid * 4 + 3] = bx.w;
        out[NB * MAXD * 4 + b * MAXD + tid]             = so;
        out[NB * MAXD * 4 + NB * MAXD + b * MAXD + tid] = cls;
    }
    __syncthreads();
    if (tid == 0) out[NB * MAXD * 6 + b] = (float)vc;
}

// =====================================================================
extern "C" void kernel_launch(void* const* d_in, const int* in_sizes, int n_in,
                              void* d_out, int out_size) {
    (void)in_sizes; (void)n_in; (void)out_size;
    const float* pred    = (const float*)d_in[1];
    const float* anchors = (const float*)d_in[2];
    float* out = (float*)d_out;

    k_nop<<<1, 32>>>();                      // ncu window lands on k_select
    k_zero<<<80, 256>>>();
    k_decode<<<NB * 600, 256>>>(pred);

    cudaFuncSetAttribute(k_select, cudaFuncAttributeMaxDynamicSharedMemorySize, 17920);
    k_select<<<NTASK, 256, 17920>>>(pred, anchors);

    k_final<<<NB, 256>>>(out);
}

// round 13
// speedup vs baseline: 5.0068x; 1.0585x over previous
#include <cuda_runtime.h>
#include <math.h>

#define A_N    76725
#define NCLS   80
#define NB     8
#define NTASK  (NB*NCLS)
#define KPRE   256
#define MDPC   100
#define MAXD   100
#define CCAP   3072
#define BUFN   1024
#define NBIN2  2048
#define NBINF  4096
#define PUSH_T 2.5f
#define CNTSTR 32
#define SEL_BASE 0xBF600000u
#define FIN_BASE 0xBD400000u

__device__ unsigned long long g_cand[(size_t)NTASK * CCAP];
__device__ int    g_cnt[NTASK * CNTSTR];
__device__ float  g_cls_scores[NTASK * MDPC];
__device__ float4 g_cls_boxes[NTASK * MDPC];

__device__ __forceinline__ unsigned fkey32(float x) {
    unsigned b = __float_as_uint(x);
    return (b & 0x80000000u) ? ~b : (b | 0x80000000u);
}

// legacy barrier-scan (fallback + k_final)
template <int BPT>
__device__ __forceinline__ unsigned suffix_total(const unsigned* hist, unsigned* csum, int tid) {
    unsigned s = 0;
    const int base = tid * BPT;
#pragma unroll
    for (int r = 0; r < BPT; ++r) s += hist[base + r];
    csum[tid] = s;
    __syncthreads();
    for (int off = 1; off < 256; off <<= 1) {
        unsigned add = (tid + off < 256) ? csum[tid + off] : 0u;
        __syncthreads();
        csum[tid] += add;
        __syncthreads();
    }
    return csum[0];
}

template <int BPT>
__device__ __forceinline__ void crossing(const unsigned* hist, const unsigned* csum, int* ctrl,
                                         unsigned target, int tid) {
    unsigned run = (tid + 1 < 256) ? csum[tid + 1] : 0u;
    const int base = tid * BPT;
    for (int i = base + BPT - 1; i >= base; --i) {
        unsigned h = hist[i];
        run += h;
        if (run >= target && run - h < target) { ctrl[0] = i; ctrl[1] = (int)(run - h); }
    }
    __syncthreads();
}

// shuffle-based inclusive suffix over 256 per-thread sums; 2 barriers total.
__device__ __forceinline__ unsigned suffix_scan(unsigned s, int tid, volatile unsigned* wtot) {
    unsigned v = s;
    const int lane = tid & 31;
#pragma unroll
    for (int off = 1; off < 32; off <<= 1) {
        unsigned t = __shfl_down_sync(0xFFFFFFFFu, v, off);
        if (lane + off < 32) v += t;
    }
    const int w = tid >> 5;
    if (lane == 0) wtot[w] = v;
    __syncthreads();
    if (tid == 0) {
        unsigned run = 0;
        for (int i = 7; i >= 0; --i) { unsigned t2 = wtot[i]; wtot[i] = run; run += t2; }
        wtot[8] = run;
    }
    __syncthreads();
    return v + wtot[w];
}

__device__ __forceinline__ void crossing2(const unsigned* hist, unsigned runstart, int* ctrl,
                                          unsigned target, int tid) {
    unsigned run = runstart;
    const int base = tid * 8;
#pragma unroll
    for (int i = base + 7; i >= base; --i) {
        unsigned h = hist[i];
        run += h;
        if (run >= target && run - h < target) { ctrl[0] = i; ctrl[1] = (int)(run - h); }
    }
    __syncthreads();
}

// =====================================================================
__global__ void k_nop() {}

__global__ void k_zero() {
    int i = blockIdx.x * 256 + threadIdx.x;
    if (i < NTASK * CNTSTR) g_cnt[i] = 0;
}

// =====================================================================
// Kernel 1: stream predictions; hierarchical threshold test
// =====================================================================
__device__ __forceinline__ void dec_push(float x, int col, int b, int a) {
    if (col >= 4 && x > PUSH_T) {
        int task = b * NCLS + (col - 4);
        float s = 1.0f / (1.0f + expf(-x));
        int idx = atomicAdd(&g_cnt[task * CNTSTR], 1);
        if (idx < CCAP) {
            unsigned key = __float_as_uint(s) | 0x80000000u;
            g_cand[(size_t)task * CCAP + idx] =
                ((unsigned long long)key << 32) | (unsigned)(~(unsigned)a);
        }
    }
}

__device__ __forceinline__ void dec_process(float4 v, int i, int b, int a0) {
    float m = fmaxf(fmaxf(v.x, v.y), fmaxf(v.z, v.w));
    if (m > PUSH_T) {
        int la   = i / 21;
        int col0 = (i - la * 21) * 4;
        int a    = a0 + la;
        dec_push(v.x, col0,     b, a);
        dec_push(v.y, col0 + 1, b, a);
        dec_push(v.z, col0 + 2, b, a);
        dec_push(v.w, col0 + 3, b, a);
    }
}

__global__ void __launch_bounds__(256) k_decode(const float* __restrict__ pred) {
    const int nT = 600;
    const int b  = blockIdx.x / nT;
    const int t  = blockIdx.x % nT;
    const int a0 = t << 7;
    const int na = min(128, A_N - a0);
    const float4* src = (const float4*)(pred + ((size_t)b * A_N + a0) * 84);
    const int tid = threadIdx.x;
    const int tot = na * 21;

    int base = 0;
    for (; base + 1024 <= tot; base += 1024) {
        float4 v0 = src[base + tid];
        float4 v1 = src[base + tid + 256];
        float4 v2 = src[base + tid + 512];
        float4 v3 = src[base + tid + 768];
        dec_process(v0, base + tid,       b, a0);
        dec_process(v1, base + tid + 256, b, a0);
        dec_process(v2, base + tid + 512, b, a0);
        dec_process(v3, base + tid + 768, b, a0);
    }
    {
        int i0 = base + tid, i1 = i0 + 256, i2 = i1 + 256;
        float4 v0, v1, v2;
        bool p0 = i0 < tot, p1 = i1 < tot, p2 = i2 < tot;
        if (p0) v0 = src[i0];
        if (p1) v1 = src[i1];
        if (p2) v2 = src[i2];
        if (p0) dec_process(v0, i0, b, a0);
        if (p1) dec_process(v1, i1, b, a0);
        if (p2) dec_process(v2, i2, b, a0);
    }
}

// =====================================================================
// Kernel 2: per (b,c) exact top-256 + greedy NMS + per-class top-100
// =====================================================================
__global__ void __launch_bounds__(256, 6) k_select(const float* __restrict__ pred,
                                                   const float* __restrict__ anchors) {
    extern __shared__ unsigned char sm[];
    unsigned*           hist = (unsigned*)sm;                      // 8KB
    unsigned*           csum = (unsigned*)(sm + 8192);             // 257 u32 (fallback)
    int*                ctrl = (int*)(sm + 9232);                  // 8 int
    unsigned long long* TIE  = (unsigned long long*)(sm + 9472);   // 32 u64
    unsigned long long* BUF  = (unsigned long long*)(sm + 9728);   // 8KB

    const int tid  = threadIdx.x;
    const int task = blockIdx.x;
    const int b    = task / NCLS;
    const int c    = task % NCLS;

    const int n = g_cnt[task * CNTSTR];
    bool fallback = !(n >= KPRE && n <= CCAP);
    const unsigned long long* cand = g_cand + (size_t)task * CCAP;

    for (int i = tid; i < NBIN2; i += 256) hist[i] = 0;
    if (tid < 8) ctrl[tid] = 0;
    __syncthreads();

    if (!fallback) {
        for (int i = tid; i < n; i += 256) {
            unsigned key = (unsigned)(cand[i] >> 32);
            unsigned bin = (key - SEL_BASE) >> 10; if (bin > 2047u) bin = 2047u;
            atomicAdd(&hist[bin], 1u);
        }
        __syncthreads();
        unsigned s8 = 0;
        {
            const int base = tid * 8;
#pragma unroll
            for (int r = 0; r < 8; ++r) s8 += hist[base + r];
        }
        unsigned incl = suffix_scan(s8, tid, csum);
        crossing2(hist, incl - s8, ctrl, KPRE, tid);
        const unsigned B1 = (unsigned)ctrl[0];
        const unsigned C1 = (unsigned)ctrl[1];
        const unsigned tie = hist[B1];
        __syncthreads();

        if (tie <= 32u) {
            // exact: strictly-above into BUF, tie bin into TIE (warp-sorted)
            if (tid == 0) { ctrl[2] = 0; ctrl[3] = 0; }
            __syncthreads();
            for (int i = tid; i < n; i += 256) {
                unsigned long long e = cand[i];
                unsigned key = (unsigned)(e >> 32);
                unsigned bin = (key - SEL_BASE) >> 10; if (bin > 2047u) bin = 2047u;
                if (bin > B1) {
                    int p = atomicAdd(&ctrl[2], 1);
                    BUF[p] = e;
                } else if (bin == B1) {
                    int q = atomicAdd(&ctrl[3], 1);
                    TIE[q] = e;
                }
            }
            __syncthreads();
            if (tid < 32) {
                const int t2 = ctrl[3];
                unsigned long long v = (tid < t2) ? TIE[tid] : 0ull;
                // warp bitonic sort ascending (zeros sink to low lanes)
#pragma unroll
                for (int k = 2; k <= 32; k <<= 1) {
#pragma unroll
                    for (int j = k >> 1; j > 0; j >>= 1) {
                        unsigned long long o = __shfl_xor_sync(0xFFFFFFFFu, v, j);
                        bool dir   = ((tid & k) == 0);
                        bool lower = ((tid & j) == 0);
                        bool keepMin = (lower == dir);
                        unsigned long long mn = v < o ? v : o;
                        unsigned long long mx = v < o ? o : v;
                        v = keepMin ? mn : mx;
                    }
                }
                int rankDesc = 31 - tid;                 // 0 = largest
                int needTie = KPRE - (int)C1;
                if (rankDesc < needTie) BUF[C1 + rankDesc] = v;
            }
            __syncthreads();
            if (tid == 0) ctrl[2] = KPRE;
            __syncthreads();
        } else {
            // whole-bin path (tie bin too large for warp sort)
            const unsigned need = C1 + tie;
            if (need <= (unsigned)BUFN) {
                const unsigned minKey = SEL_BASE + (B1 << 10);
                if (tid == 0) ctrl[2] = 0;
                __syncthreads();
                for (int i = tid; i < n; i += 256) {
                    unsigned long long e = cand[i];
                    if ((unsigned)(e >> 32) >= minKey) {
                        int p = atomicAdd(&ctrl[2], 1);
                        BUF[p] = e;
                    }
                }
                __syncthreads();
            } else {
                fallback = true;
            }
        }
    }

    if (fallback) {
        for (int i = tid; i < NBIN2; i += 256) hist[i] = 0;
        if (tid < 8) ctrl[tid] = 0;
        __syncthreads();
        unsigned cnt = 0;
        for (int a = tid; a < A_N; a += 256) {
            float x = pred[((size_t)b * A_N + a) * 84 + 4 + c];
            float s = 1.0f / (1.0f + expf(-x));
            if (s > 0.05f) { ++cnt; atomicAdd(&hist[fkey32(s) >> 21], 1u); }
        }
        for (int o = 16; o; o >>= 1) cnt += __shfl_down_sync(0xFFFFFFFFu, cnt, o);
        if ((tid & 31) == 0) atomicAdd((unsigned*)&ctrl[5], cnt);
        __syncthreads();
        const unsigned total = (unsigned)ctrl[5];
        if (total == 0u) {
            for (int p = tid; p < MDPC; p += 256) {
                g_cls_scores[task * MDPC + p] = -1.0f;
                g_cls_boxes [task * MDPC + p] = make_float4(0.f, 0.f, 0.f, 0.f);
            }
            return;
        }
        const unsigned target = total < (unsigned)KPRE ? total : (unsigned)KPRE;
        (void)suffix_total<8>(hist, csum, tid);
        crossing<8>(hist, csum, ctrl, target, tid);
        const unsigned B1 = (unsigned)ctrl[0];
        const unsigned C1 = (unsigned)ctrl[1];
        __syncthreads();
        for (int i = tid; i < NBIN2; i += 256) hist[i] = 0;
        __syncthreads();
        for (int a = tid; a < A_N; a += 256) {
            float x = pred[((size_t)b * A_N + a) * 84 + 4 + c];
            float s = 1.0f / (1.0f + expf(-x));
            if (s > 0.05f) {
                unsigned key = fkey32(s);
                if ((key >> 21) == B1) atomicAdd(&hist[(key >> 10) & 0x7FFu], 1u);
            }
        }
        __syncthreads();
        (void)suffix_total<8>(hist, csum, tid);
        crossing<8>(hist, csum, ctrl, target - C1, tid);
        const unsigned B2 = (unsigned)ctrl[0];
        if (tid == 0) ctrl[2] = 0;
        __syncthreads();
        for (int a = tid; a < A_N; a += 256) {
            float x = pred[((size_t)b * A_N + a) * 84 + 4 + c];
            float s = 1.0f / (1.0f + expf(-x));
            if (s > 0.05f) {
                unsigned key = fkey32(s);
                unsigned l1 = key >> 21;
                bool take = l1 > B1 || (l1 == B1 && ((key >> 10) & 0x7FFu) >= B2);
                if (take) {
                    int p = atomicAdd(&ctrl[2], 1);
                    if (p < BUFN)
                        BUF[p] = ((unsigned long long)key << 32) | (unsigned)(~(unsigned)a);
                }
            }
        }
        __syncthreads();
    }

    int sel = ctrl[2]; if (sel > BUFN) sel = BUFN;
    const int W = (sel <= 256) ? 256 : ((sel <= 512) ? 512 : 1024);
    for (int i = sel + tid; i < W; i += 256) BUF[i] = 0ull;
    __syncthreads();

    for (int kk = 2; kk <= W; kk <<= 1) {
        for (int j = kk >> 1; j > 0; j >>= 1) {
            for (int i = tid; i < W; i += 256) {
                int ix = i ^ j;
                if (ix > i) {
                    unsigned long long x = BUF[i], y = BUF[ix];
                    bool sw = ((i & kk) == 0) ? (x < y) : (x > y);
                    if (sw) { BUF[i] = y; BUF[ix] = x; }
                }
            }
            __syncthreads();
        }
    }

    // ---- NMS on top-256 ----
    float4*   BXS   = (float4*)sm;               // [256] = 4KB
    float*    AR    = (float*)(sm + 4096);
    float*    SC    = (float*)(sm + 5120);
    unsigned* MASKS = (unsigned*)(sm + 6144);    // [256][8]
    unsigned* KEEPW = (unsigned*)(sm + 14336);
    unsigned* WPFX  = (unsigned*)(sm + 14400);

    float ax1, ay1, ax2, ay2, aa;
    {
        unsigned long long e = BUF[tid];
        unsigned key  = (unsigned)(e >> 32);
        unsigned aidx = ~(unsigned)(e & 0xFFFFFFFFull);
        float  s  = -1.0f;
        float4 bx = make_float4(0.f, 0.f, 0.f, 0.f);
        if (key) {
            const float4 bp = *(const float4*)(pred + ((size_t)b * A_N + aidx) * 84);
            const float4 an = ((const float4*)anchors)[aidx];
            float cx = bp.x * 0.1f * an.z + an.x;
            float cy = bp.y * 0.1f * an.w + an.y;
            float w  = expf(bp.z * 0.2f) * an.z;
            float h  = expf(bp.w * 0.2f) * an.w;
            bx = make_float4(cx - w * 0.5f, cy - h * 0.5f, cx + w * 0.5f, cy + h * 0.5f);
            s  = __uint_as_float(key & 0x7FFFFFFFu);
        }
        BXS[tid] = bx;
        ax1 = bx.x; ay1 = bx.y; ax2 = bx.z; ay2 = bx.w;
        aa  = (bx.z - bx.x) * (bx.w - bx.y);
        AR[tid] = aa;
        SC[tid] = s;
        unsigned bal = __ballot_sync(0xFFFFFFFFu, key != 0u);
        if ((tid & 31) == 0) KEEPW[tid >> 5] = bal;
#pragma unroll
        for (int w = 0; w < 8; ++w) MASKS[tid * 8 + w] = 0u;
    }
    __syncthreads();

    {   // balanced all-pairs mask: wrapped pairing, one LDS.128 per pair
        for (int k = 1; k <= 128; ++k) {
            if (k == 128 && tid >= 128) break;
            int j = (tid + k) & 255;
            float4 bj = BXS[j];
            float iw = fmaxf(fminf(ax2, bj.z) - fmaxf(ax1, bj.x), 0.f);
            float ih = fmaxf(fminf(ay2, bj.w) - fmaxf(ay1, bj.y), 0.f);
            float inter = iw * ih;
            float arj = (bj.z - bj.x) * (bj.w - bj.y);
            float thr = 0.5f * fmaxf(aa + arj - inter, 1e-8f);
            if (inter > thr) {
                int lo = tid < j ? tid : j;
                int hi = tid ^ j ^ lo;
                atomicOr(&MASKS[lo * 8 + (hi >> 5)], 1u << (hi & 31));
            }
        }
    }
    __syncthreads();

    if (tid < 32) {   // greedy pass with early exit at 100 keepers
        unsigned kw = (tid < 8) ? KEEPW[tid] : 0u;
        int kcnt = 0;
        for (int i = 0; i < 256 && kcnt < MDPC; ++i) {
            unsigned word = __shfl_sync(0xFFFFFFFFu, kw, i >> 5);
            if ((word >> (i & 31)) & 1u) {
                ++kcnt;
                if (tid < 8) kw &= ~MASKS[i * 8 + tid];
            }
        }
        if (tid < 8) KEEPW[tid] = kw;
    }
    __syncthreads();

    if (tid == 0) {
        unsigned run = 0;
        for (int w = 0; w < 8; ++w) { WPFX[w] = run; run += __popc(KEEPW[w]); }
        WPFX[8] = run;
    }
    __syncthreads();

    {
        unsigned w = tid >> 5, bpos = tid & 31;
        unsigned kwv = KEEPW[w];
        bool kept = (kwv >> bpos) & 1u;
        unsigned p = WPFX[w] + __popc(kwv & ((1u << bpos) - 1u));
        if (kept && p < MDPC) {
            g_cls_scores[task * MDPC + p] = SC[tid];
            g_cls_boxes [task * MDPC + p] = BXS[tid];
        }
        int kc = (int)WPFX[8];
        for (int q = kc + tid; q < MDPC; q += 256) {
            g_cls_scores[task * MDPC + q] = -1.0f;
            g_cls_boxes [task * MDPC + q] = make_float4(0.f, 0.f, 0.f, 0.f);
        }
    }
}

// =====================================================================
// Kernel 3: per image top-100 of 8000
// =====================================================================
__global__ void __launch_bounds__(256) k_final(float* __restrict__ out) {
    __shared__ unsigned hist[NBINF];
    __shared__ unsigned long long BUF[256];
    __shared__ unsigned csum[257];
    __shared__ int ctrl[8];
    __shared__ int vc;

    const int tid = threadIdx.x;
    const int b   = blockIdx.x;
    const float* sc = g_cls_scores + b * NCLS * MDPC;

    for (int i = tid; i < NBINF; i += 256) hist[i] = 0;
    if (tid < 8) ctrl[tid] = 0;
    __syncthreads();

    unsigned cnt = 0;
    for (int i = tid; i < NCLS * MDPC; i += 256) {
        float s = sc[i];
        if (s > 0.0f) { ++cnt; atomicAdd(&hist[(fkey32(s) - FIN_BASE) >> 14], 1u); }
    }
    for (int o = 16; o; o >>= 1) cnt += __shfl_down_sync(0xFFFFFFFFu, cnt, o);
    if ((tid & 31) == 0) atomicAdd((unsigned*)&ctrl[5], cnt);
    __syncthreads();
    const unsigned npos = (unsigned)ctrl[5];

    if (npos >= (unsigned)MAXD) {
        (void)suffix_total<16>(hist, csum, tid);
        crossing<16>(hist, csum, ctrl, MAXD, tid);
        const unsigned B1 = (unsigned)ctrl[0];
        const unsigned C1 = (unsigned)ctrl[1];
        __syncthreads();
        for (int i = tid; i < NBINF; i += 256) hist[i] = 0;
        __syncthreads();
        for (int i = tid; i < NCLS * MDPC; i += 256) {
            float s = sc[i];
            if (s > 0.0f) {
                unsigned key = fkey32(s);
                if (((key - FIN_BASE) >> 14) == B1) atomicAdd(&hist[(key >> 2) & 0xFFFu], 1u);
            }
        }
        __syncthreads();
        (void)suffix_total<16>(hist, csum, tid);
        crossing<16>(hist, csum, ctrl, MAXD - C1, tid);
        const unsigned B2 = (unsigned)ctrl[0];
        if (tid == 0) ctrl[2] = 0;
        __syncthreads();
        for (int i = tid; i < NCLS * MDPC; i += 256) {
            float s = sc[i];
            if (s > 0.0f) {
                unsigned key = fkey32(s);
                unsigned l1 = (key - FIN_BASE) >> 14;
                bool take = l1 > B1 || (l1 == B1 && ((key >> 2) & 0xFFFu) >= B2);
                if (take) {
                    int p = atomicAdd(&ctrl[2], 1);
                    if (p < 256)
                        BUF[p] = ((unsigned long long)key << 32) | (unsigned)(~(unsigned)i);
                }
            }
        }
        __syncthreads();
    } else {
        if (tid == 0) ctrl[2] = 0;
        __syncthreads();
        for (int i = tid; i < NCLS * MDPC; i += 256) {
            float s = sc[i];
            if (s > 0.0f) {
                int p = atomicAdd(&ctrl[2], 1);
                if (p < 256)
                    BUF[p] = ((unsigned long long)fkey32(s) << 32) | (unsigned)(~(unsigned)i);
            }
        }
        __syncthreads();
    }

    int sel = ctrl[2]; if (sel > 256) sel = 256;
    if (tid >= sel) BUF[tid] = 0ull;
    __syncthreads();

    for (int kk = 2; kk <= 256; kk <<= 1) {
        for (int j = kk >> 1; j > 0; j >>= 1) {
            int ix = tid ^ j;
            if (ix > tid) {
                unsigned long long x = BUF[tid], y = BUF[ix];
                bool sw = ((tid & kk) == 0) ? (x < y) : (x > y);
                if (sw) { BUF[tid] = y; BUF[ix] = x; }
            }
            __syncthreads();
        }
    }

    if (tid == 0) vc = 0;
    __syncthreads();

    if (tid < MAXD) {
        unsigned long long e = BUF[tid];
        unsigned key  = (unsigned)(e >> 32);
        unsigned flat = ~(unsigned)(e & 0xFFFFFFFFull);
        bool valid = (key != 0u);
        float4 bx = make_float4(0.f, 0.f, 0.f, 0.f);
        float cls = 0.0f, so = 0.0f;
        if (valid) {
            float s = __uint_as_float((key & 0x80000000u) ? (key & 0x7FFFFFFFu) : ~key);
            bx  = g_cls_boxes[b * NCLS * MDPC + flat];
            cls = (float)(flat / MDPC);
            so  = s;
            atomicAdd(&vc, 1);
        }
        out[b * 400 + tid * 4 + 0] = bx.x;
        out[b * 400 + tid * 4 + 1] = bx.y;
        out[b * 400 + tid * 4 + 2] = bx.z;
        out[b * 400 + tid * 4 + 3] = bx.w;
        out[NB * MAXD * 4 + b * MAXD + tid]             = so;
        out[NB * MAXD * 4 + NB * MAXD + b * MAXD + tid] = cls;
    }
    __syncthreads();
    if (tid == 0) out[NB * MAXD * 6 + b] = (float)vc;
}

// =====================================================================
extern "C" void kernel_launch(void* const* d_in, const int* in_sizes, int n_in,
                              void* d_out, int out_size) {
    (void)in_sizes; (void)n_in; (void)out_size;
    const float* pred    = (const float*)d_in[1];
    const float* anchors = (const float*)d_in[2];
    float* out = (float*)d_out;

    k_nop<<<1, 32>>>();                      // ncu window lands on k_select
    k_zero<<<80, 256>>>();
    k_decode<<<NB * 600, 256>>>(pred);

    cudaFuncSetAttribute(k_select, cudaFuncAttributeMaxDynamicSharedMemorySize, 17920);
    k_select<<<NTASK, 256, 17920>>>(pred, anchors);

    k_final<<<NB, 256>>>(out);
}